// round 9
// baseline (speedup 1.0000x reference)
#include <cuda_runtime.h>
#include <stdint.h>
#include <math.h>

#define Bb   16
#define Cc   128
#define Hh   64
#define Ww   64
#define HID  128
#define OC   512   // 4*HID
#define NCTA 128   // 16 b x 8 hid-blocks, all co-resident (<=148 SMs, 1 CTA/SM)

typedef unsigned long long u64;

// Scratch (device globals: allocation-free per harness rules)
__device__ float    g_zis[(size_t)Bb*OC*Hh*Ww];   // [b, o, h, w]  134 MB
__device__ float    g_hbuf[2][Bb*HID*Ww];         // double-buffered hidden state
__device__ unsigned g_cnt[16*32];                 // per-batch barrier counters (128B apart)

// ---- packed f32x2 helpers (sm_103a) --------------------------------------
#define PACK2(d, lo, hi) asm("mov.b64 %0, {%1,%2};" : "=l"(d) : "f"(lo), "f"(hi))
#define FMA2(d, a, b, c) asm("fma.rn.f32x2 %0, %1, %2, %3;" : "=l"(d) : "l"(a), "l"(b), "l"(c))
#define UNPK2(lo, hi, s) asm("mov.b64 {%0,%1}, %2;" : "=f"(lo), "=f"(hi) : "l"(s))

__device__ __forceinline__ unsigned ld_acq_gpu(const unsigned* p) {
    unsigned v;
    asm volatile("ld.global.acquire.gpu.u32 %0, [%1];" : "=r"(v) : "l"(p) : "memory");
    return v;
}
__device__ __forceinline__ void red_rel_gpu(unsigned* p, unsigned v) {
    asm volatile("red.release.gpu.global.add.u32 [%0], %1;" :: "l"(p), "r"(v) : "memory");
}

// ---------------------------------------------------------------------------
__global__ void init_kernel() {
    int i = threadIdx.x;
    if (i < 16*32) g_cnt[i] = 0u;
}

// ---------------------------------------------------------------------------
// Phase 1: masked input-to-state conv (taps k=0,1; k=2 masked away).
// grid (B*H, OC/64), block 512: tx=tid&15 (4 w each), typ=tid>>4 (o-pair 0..31).
__global__ void __launch_bounds__(512)
kA_zis(const float* __restrict__ x,
       const float* __restrict__ Wis,
       const float* __restrict__ bis) {
    extern __shared__ float sm[];
    float* wt = sm;               // [c][32][4]   16384 floats
    float* xs = sm + 16384;       // [c][64]       8192 floats

    int b  = blockIdx.x >> 6;
    int h  = blockIdx.x & 63;
    int o0 = blockIdx.y * 64;
    int tid = threadIdx.x;

    for (int idx = tid; idx < 8192; idx += 512)
        xs[idx] = x[(((size_t)b*Cc + (idx >> 6))*Hh + h)*Ww + (idx & 63)];

    {   // coalesced weight read, scatter taps 0,1 into paired layout
        const float* wsrc = Wis + (size_t)o0 * (Cc*3);
        for (int idx = tid; idx < 64*Cc*3; idx += 512) {
            float v = wsrc[idx];
            int ol  = idx / (Cc*3);
            int rem = idx - ol*(Cc*3);
            int c   = rem / 3;
            int k   = rem - c*3;
            if (k < 2) wt[(c*32 + (ol >> 1))*4 + k*2 + (ol & 1)] = v;
        }
    }
    __syncthreads();

    int tx  = tid & 15;
    int typ = tid >> 4;            // o-pair index 0..31
    int wb  = tx * 4;

    u64 acc[4] = {0ull, 0ull, 0ull, 0ull};

#pragma unroll 2
    for (int c = 0; c < 128; ++c) {
        const float* xr = &xs[c*64 + wb];
        float4 xv = *reinterpret_cast<const float4*>(xr);
        float xm1 = (wb == 0) ? 0.f : xr[-1];
        float hv[5] = {xm1, xv.x, xv.y, xv.z, xv.w};
        u64 hp[5];
#pragma unroll
        for (int t = 0; t < 5; ++t) PACK2(hp[t], hv[t], hv[t]);
        ulonglong2 w01 = *reinterpret_cast<const ulonglong2*>(&wt[(c*32 + typ)*4]);
#pragma unroll
        for (int i = 0; i < 4; ++i) {
            FMA2(acc[i], w01.x, hp[i],   acc[i]);   // tap k=0 uses x[w-1]
            FMA2(acc[i], w01.y, hp[i+1], acc[i]);   // tap k=1 uses x[w]
        }
    }

    float lo[4], hi[4];
#pragma unroll
    for (int i = 0; i < 4; ++i) UNPK2(lo[i], hi[i], acc[i]);
    int oA = o0 + typ*2;
    float bA = bis[oA], bB = bis[oA+1];
    float4 rA = {lo[0]+bA, lo[1]+bA, lo[2]+bA, lo[3]+bA};
    float4 rB = {hi[0]+bB, hi[1]+bB, hi[2]+bB, hi[3]+bB};
    *reinterpret_cast<float4*>(&g_zis[(((size_t)b*OC + oA  )*Hh + h)*Ww + wb]) = rA;
    *reinterpret_cast<float4*>(&g_zis[(((size_t)b*OC + oA+1)*Hh + h)*Ww + wb]) = rB;
}

// ---------------------------------------------------------------------------
// Phase 2: persistent fused recurrence, 128 CTAs x 512 threads, K-SPLIT by 2.
// GEMM: thread = (ks, typ, tx): 8 w (wb=8*tx) x 1 o-pair, c in [ks*64,ks*64+64).
// Gates: thread = (cg, w): lane-consecutive w, 2 hid channels (cg, cg+8).
// h exchanged via L2 (g_hbuf) + per-batch release/acquire counter barrier.
#define HSTR 72
#define HS1  (128*HSTR)
#define ZB1  (64*66)
__global__ void __launch_bounds__(512, 1)
kP_rows(const float* __restrict__ Wss,
        const float* __restrict__ bss,
        float* __restrict__ out) {
    extern __shared__ float sm[];
    float* wk01 = sm;                    // [c][32][4]  k0/k1 o-pairs, 16384 f
    float* wk2  = sm + 16384;            // [c][32][2]  k2 o-pairs,     8192 f
    float* hs   = wk2 + 8192;            // [128][72]  h[w] at c*72+4+w, 9216 f
    float* zbuf = hs + HS1;              // [2][64][66]                 8448 f

    int b   = blockIdx.x >> 3;
    int hb  = blockIdx.x & 7;
    int tid = threadIdx.x;
    int ks  = tid >> 8;                  // K-split half: c in [ks*64, ks*64+64)
    int t2  = tid & 255;
    int tx  = t2 & 7;                    // 8 w per thread
    int typ = t2 >> 3;                   // o-pair 0..31
    int wb  = tx * 8;

    unsigned* cnt = &g_cnt[b*32];

    // Load W_ss once: o_local = g*16 + l  ->  global o = g*128 + hb*16 + l
    for (int idx = tid; idx < 64*HID*3; idx += 512) {
        int ol  = idx / (HID*3);
        int rem = idx - ol*(HID*3);
        int g   = ol >> 4, l = ol & 15;
        int o   = g*128 + hb*16 + l;
        float v = Wss[(size_t)o*(HID*3) + rem];
        int c = rem / 3, k = rem - c*3;
        int pr = ol >> 1, ln = ol & 1;
        if (k < 2) wk01[(c*32 + pr)*4 + k*2 + ln] = v;
        else       wk2 [(c*32 + pr)*2 + ln] = v;
    }
    // zero hs once (halo columns at +0..3 and +68..71 stay 0 forever)
    for (int idx = tid; idx < HS1; idx += 512) hs[idx] = 0.f;

    // gate-phase mapping: lane-consecutive w, 2 channels per thread
    int w  = tid & 63;
    int cg = tid >> 6;                   // 0..7; channels cg and cg+8
    int ch0 = hb*16 + cg;
    int ch1 = hb*16 + cg + 8;

    float sbv[8];
#pragma unroll
    for (int g = 0; g < 4; ++g) {
        sbv[g*2]     = bss[g*128 + ch0];
        sbv[g*2 + 1] = bss[g*128 + ch1];
    }

    float cst[2] = {0.f, 0.f};           // cell state (2 channels, 1 w)

    const float* zisb = g_zis + (size_t)b*OC*Hh*Ww;
    const int cbase = ks * 64;
    __syncthreads();

    for (int r = 0; r < Hh; ++r) {
        // prefetch z_is for the gate phase (independent of barrier -> overlaps poll)
        float zvv[8];
#pragma unroll
        for (int g = 0; g < 4; ++g) {
            zvv[g*2]     = zisb[(((size_t)(g*128 + ch0))*Hh + r)*Ww + w];
            zvv[g*2 + 1] = zisb[(((size_t)(g*128 + ch1))*Hh + r)*Ww + w];
        }

        u64 acc[8] = {0ull,0ull,0ull,0ull,0ull,0ull,0ull,0ull};

        if (r > 0) {
            // wait for all 8 CTAs of this b to have published row r-1
            if (tid == 0) {
                unsigned target = 8u * (unsigned)r;
                while (ld_acq_gpu(cnt) < target) __nanosleep(64);
            }
            __syncthreads();
            // reload h (float4, L2) into smem
            const float4* hsrc = reinterpret_cast<const float4*>(
                g_hbuf[(r-1) & 1] + b*HID*Ww);
#pragma unroll
            for (int it = 0; it < 4; ++it) {
                int j = tid + it*512;          // float4 index, 2048 total
                int c = j >> 4, w4 = (j & 15) * 4;
                float4 v = __ldcg(&hsrc[j]);
                *reinterpret_cast<float4*>(&hs[c*HSTR + 4 + w4]) = v;
            }
            __syncthreads();

#pragma unroll 2
            for (int cc = 0; cc < 64; ++cc) {
                int c = cbase + cc;
                const float* hrow = &hs[c*HSTR + wb];
                float  hm1 = hrow[3];                                     // h[wb-1]
                float4 v0  = *reinterpret_cast<const float4*>(hrow + 4);  // h[wb..wb+3]
                float4 v1  = *reinterpret_cast<const float4*>(hrow + 8);  // h[wb+4..wb+7]
                float  h8  = hrow[12];                                    // h[wb+8]
                float hv[10] = {hm1, v0.x,v0.y,v0.z,v0.w, v1.x,v1.y,v1.z,v1.w, h8};
                u64 hp[10];
#pragma unroll
                for (int t = 0; t < 10; ++t) PACK2(hp[t], hv[t], hv[t]);
                ulonglong2 wA = *reinterpret_cast<const ulonglong2*>(&wk01[(c*32 + typ)*4]);
                u64        w2 = *reinterpret_cast<const u64*>(&wk2[(c*32 + typ)*2]);
#pragma unroll
                for (int i = 0; i < 8; ++i) {
                    FMA2(acc[i], wA.x, hp[i],   acc[i]);
                    FMA2(acc[i], wA.y, hp[i+1], acc[i]);
                    FMA2(acc[i], w2,   hp[i+2], acc[i]);
                }
            }
        }

        // stage partial z_ss into zbuf[ks][w][o_local] (o pairs contiguous)
        {
            float* zb = zbuf + ks*ZB1;
#pragma unroll
            for (int i = 0; i < 8; ++i)
                *reinterpret_cast<u64*>(&zb[(wb + i)*66 + typ*2]) = acc[i];
        }
        __syncthreads();

        // gates for channels (ch0, ch1) at column w; z = partialA + partialB
        float hres[2];
#pragma unroll
        for (int j = 0; j < 2; ++j) {
            int cl = cg + j*8;
            float zi = zbuf[w*66 +  0 + cl] + zbuf[ZB1 + w*66 +  0 + cl] + sbv[0*2+j] + zvv[0*2+j];
            float zf = zbuf[w*66 + 16 + cl] + zbuf[ZB1 + w*66 + 16 + cl] + sbv[1*2+j] + zvv[1*2+j];
            float zo = zbuf[w*66 + 32 + cl] + zbuf[ZB1 + w*66 + 32 + cl] + sbv[2*2+j] + zvv[2*2+j];
            float zg = zbuf[w*66 + 48 + cl] + zbuf[ZB1 + w*66 + 48 + cl] + sbv[3*2+j] + zvv[3*2+j];
            float ig = 1.f / (1.f + __expf(-zi));
            float fg = 1.f / (1.f + __expf(-zf));
            float og = 1.f / (1.f + __expf(-zo));
            float gg = tanhf(zg);
            float cn = fg*cst[j] + ig*gg;
            cst[j] = cn;
            hres[j] = og * tanhf(cn);
        }
        out[(((size_t)b*HID + ch0)*Hh + r)*Ww + w] = hres[0];
        out[(((size_t)b*HID + ch1)*Hh + r)*Ww + w] = hres[1];

        if (r < Hh - 1) {
            // publish h_r (coalesced scalar stcg), then release-arrive
            __stcg(&g_hbuf[r & 1][(b*HID + ch0)*Ww + w], hres[0]);
            __stcg(&g_hbuf[r & 1][(b*HID + ch1)*Ww + w], hres[1]);
            __syncthreads();               // all stcg done before the release
            if (tid == 0) red_rel_gpu(cnt, 1u);
        }
    }
}

// ---------------------------------------------------------------------------
extern "C" void kernel_launch(void* const* d_in, const int* in_sizes, int n_in,
                              void* d_out, int out_size) {
    const float* x   = (const float*)d_in[0];
    const float* Wis = (const float*)d_in[1];
    const float* bis = (const float*)d_in[2];
    const float* Wss = (const float*)d_in[3];
    const float* bss = (const float*)d_in[4];
    float* out = (float*)d_out;

    const int SMEM_A = (16384 + 8192)*sizeof(float);                    //  98304
    const int SMEM_P = (16384 + 8192 + HS1 + 2*ZB1)*sizeof(float);      // 168960
    cudaFuncSetAttribute(kA_zis,  cudaFuncAttributeMaxDynamicSharedMemorySize, SMEM_A);
    cudaFuncSetAttribute(kP_rows, cudaFuncAttributeMaxDynamicSharedMemorySize, SMEM_P);

    init_kernel<<<1, 512>>>();

    dim3 gA(Bb*Hh, OC/64);
    kA_zis<<<gA, 512, SMEM_A>>>(x, Wis, bis);

    kP_rows<<<NCTA, 512, SMEM_P>>>(Wss, bss, out);
}

// round 10
// speedup vs baseline: 1.1551x; 1.1551x over previous
#include <cuda_runtime.h>
#include <stdint.h>
#include <math.h>

#define Bb   16
#define Cc   128
#define Hh   64
#define Ww   64
#define HID  128
#define OC   512   // 4*HID
#define NCTA 128   // 16 b x 8 hid-blocks, all co-resident (<=148 SMs, 1 CTA/SM)

typedef unsigned long long u64;

// Scratch (device globals: allocation-free per harness rules)
__device__ float    g_zis[(size_t)Bb*OC*Hh*Ww];   // [b, o, h, w]  134 MB
__device__ float    g_hbuf[2][Bb*HID*Ww];         // double-buffered hidden state
__device__ unsigned g_cnt[16*32];                 // per-batch barrier counters (128B apart)

// ---- packed f32x2 helpers (sm_103a) --------------------------------------
#define PACK2(d, lo, hi) asm("mov.b64 %0, {%1,%2};" : "=l"(d) : "f"(lo), "f"(hi))
#define FMA2(d, a, b, c) asm("fma.rn.f32x2 %0, %1, %2, %3;" : "=l"(d) : "l"(a), "l"(b), "l"(c))
#define UNPK2(lo, hi, s) asm("mov.b64 {%0,%1}, %2;" : "=f"(lo), "=f"(hi) : "l"(s))

__device__ __forceinline__ unsigned ld_acq_gpu(const unsigned* p) {
    unsigned v;
    asm volatile("ld.global.acquire.gpu.u32 %0, [%1];" : "=r"(v) : "l"(p) : "memory");
    return v;
}
__device__ __forceinline__ void red_rel_gpu(unsigned* p, unsigned v) {
    asm volatile("red.release.gpu.global.add.u32 [%0], %1;" :: "l"(p), "r"(v) : "memory");
}

// ---------------------------------------------------------------------------
__global__ void init_kernel() {
    int i = threadIdx.x;
    if (i < 16*32) g_cnt[i] = 0u;
}

// ---------------------------------------------------------------------------
// Phase 1: masked input-to-state conv (taps k=0,1; k=2 masked away).
// grid (B*H, OC/64), block 512: tx=tid&15 (4 w each), typ=tid>>4 (o-pair 0..31).
// (unchanged from R8 — near its fp32 floor)
__global__ void __launch_bounds__(512)
kA_zis(const float* __restrict__ x,
       const float* __restrict__ Wis,
       const float* __restrict__ bis) {
    extern __shared__ float sm[];
    float* wt = sm;               // [c][32][4]   16384 floats
    float* xs = sm + 16384;       // [c][64]       8192 floats

    int b  = blockIdx.x >> 6;
    int h  = blockIdx.x & 63;
    int o0 = blockIdx.y * 64;
    int tid = threadIdx.x;

    for (int idx = tid; idx < 8192; idx += 512)
        xs[idx] = x[(((size_t)b*Cc + (idx >> 6))*Hh + h)*Ww + (idx & 63)];

    {   // coalesced weight read, scatter taps 0,1 into paired layout
        const float* wsrc = Wis + (size_t)o0 * (Cc*3);
        for (int idx = tid; idx < 64*Cc*3; idx += 512) {
            float v = wsrc[idx];
            int ol  = idx / (Cc*3);
            int rem = idx - ol*(Cc*3);
            int c   = rem / 3;
            int k   = rem - c*3;
            if (k < 2) wt[(c*32 + (ol >> 1))*4 + k*2 + (ol & 1)] = v;
        }
    }
    __syncthreads();

    int tx  = tid & 15;
    int typ = tid >> 4;            // o-pair index 0..31
    int wb  = tx * 4;

    u64 acc[4] = {0ull, 0ull, 0ull, 0ull};

#pragma unroll 2
    for (int c = 0; c < 128; ++c) {
        const float* xr = &xs[c*64 + wb];
        float4 xv = *reinterpret_cast<const float4*>(xr);
        float xm1 = (wb == 0) ? 0.f : xr[-1];
        float hv[5] = {xm1, xv.x, xv.y, xv.z, xv.w};
        u64 hp[5];
#pragma unroll
        for (int t = 0; t < 5; ++t) PACK2(hp[t], hv[t], hv[t]);
        ulonglong2 w01 = *reinterpret_cast<const ulonglong2*>(&wt[(c*32 + typ)*4]);
#pragma unroll
        for (int i = 0; i < 4; ++i) {
            FMA2(acc[i], w01.x, hp[i],   acc[i]);   // tap k=0 uses x[w-1]
            FMA2(acc[i], w01.y, hp[i+1], acc[i]);   // tap k=1 uses x[w]
        }
    }

    float lo[4], hi[4];
#pragma unroll
    for (int i = 0; i < 4; ++i) UNPK2(lo[i], hi[i], acc[i]);
    int oA = o0 + typ*2;
    float bA = bis[oA], bB = bis[oA+1];
    float4 rA = {lo[0]+bA, lo[1]+bA, lo[2]+bA, lo[3]+bA};
    float4 rB = {hi[0]+bB, hi[1]+bB, hi[2]+bB, hi[3]+bB};
    *reinterpret_cast<float4*>(&g_zis[(((size_t)b*OC + oA  )*Hh + h)*Ww + wb]) = rA;
    *reinterpret_cast<float4*>(&g_zis[(((size_t)b*OC + oA+1)*Hh + h)*Ww + wb]) = rB;
}

// ---------------------------------------------------------------------------
// Phase 2: persistent fused recurrence, 128 CTAs x 512 threads, K-SPLIT by 4.
// GEMM thread = (ks=tid>>7, ty, tx): 4 w x 4 o-pairs, c in [ks*32, ks*32+32).
// Gates (R8 mapping): cl=tid>>5, wg=(tid&31)*2; z = sum of 4 K-partials.
// h exchanged via L2 (g_hbuf) + per-batch release/acquire counter barrier.
#define HSTR 72
#define HS1  (128*HSTR)
#define ZB1  (64*66)
__global__ void __launch_bounds__(512, 1)
kP_rows(const float* __restrict__ Wss,
        const float* __restrict__ bss,
        float* __restrict__ out) {
    extern __shared__ float sm[];
    float* wk01 = sm;                    // [c][32][4]  k0/k1 o-pairs, 16384 f
    float* wk2  = sm + 16384;            // [c][32][2]  k2 o-pairs,     8192 f
    float* hs   = wk2 + 8192;            // [128][72]  h[w] at c*72+4+w, 9216 f
    float* zbuf = hs + HS1;              // [4][64][66]                16896 f

    int b   = blockIdx.x >> 3;
    int hb  = blockIdx.x & 7;
    int tid = threadIdx.x;
    int ks  = tid >> 7;                  // K-split quarter: c in [ks*32, ks*32+32)
    int t2  = tid & 127;
    int tx  = t2 & 15;                   // 4 w per thread
    int ty  = t2 >> 4;                   // o-octet 0..7 (pairs 4*ty .. 4*ty+3)
    int wb  = tx * 4;

    unsigned* cnt = &g_cnt[b*32];

    // Load W_ss once: o_local = g*16 + l  ->  global o = g*128 + hb*16 + l
    for (int idx = tid; idx < 64*HID*3; idx += 512) {
        int ol  = idx / (HID*3);
        int rem = idx - ol*(HID*3);
        int g   = ol >> 4, l = ol & 15;
        int o   = g*128 + hb*16 + l;
        float v = Wss[(size_t)o*(HID*3) + rem];
        int c = rem / 3, k = rem - c*3;
        int pr = ol >> 1, ln = ol & 1;
        if (k < 2) wk01[(c*32 + pr)*4 + k*2 + ln] = v;
        else       wk2 [(c*32 + pr)*2 + ln] = v;
    }
    // zero hs once (halo columns at +0..3 and +68..71 stay 0 forever)
    for (int idx = tid; idx < HS1; idx += 512) hs[idx] = 0.f;

    // gate-phase mapping (R8): cl channel-local, 2 consecutive w per thread
    int cl = tid >> 5;                   // hid channel local 0..15
    int wg = (tid & 31) * 2;             // w pair base
    int chg = hb*16 + cl;

    float sbv[4];
#pragma unroll
    for (int g = 0; g < 4; ++g) sbv[g] = bss[g*128 + chg];

    float cst[2] = {0.f, 0.f};           // cell state (2 w per thread)

    const float* zisb = g_zis + (size_t)b*OC*Hh*Ww;
    const int cbase = ks * 32;
    const int prb   = ty * 4;            // first o-pair of this thread
    __syncthreads();

    for (int r = 0; r < Hh; ++r) {
        // prefetch z_is for the gate phase (independent of barrier -> overlaps poll)
        float2 zv[4];
#pragma unroll
        for (int g = 0; g < 4; ++g)
            zv[g] = *reinterpret_cast<const float2*>(
                &zisb[(((size_t)(g*128 + chg))*Hh + r)*Ww + wg]);

        u64 acc[4][4];
#pragma unroll
        for (int p = 0; p < 4; ++p)
#pragma unroll
            for (int i = 0; i < 4; ++i) acc[p][i] = 0ull;

        if (r > 0) {
            // wait for all 8 CTAs of this b to have published row r-1
            if (tid == 0) {
                unsigned target = 8u * (unsigned)r;
                while (ld_acq_gpu(cnt) < target) __nanosleep(32);
            }
            __syncthreads();
            // reload h (float4, L2) into smem
            const float4* hsrc = reinterpret_cast<const float4*>(
                g_hbuf[(r-1) & 1] + b*HID*Ww);
#pragma unroll
            for (int it = 0; it < 4; ++it) {
                int j = tid + it*512;          // float4 index, 2048 total
                int c = j >> 4, w4 = (j & 15) * 4;
                float4 v = __ldcg(&hsrc[j]);
                *reinterpret_cast<float4*>(&hs[c*HSTR + 4 + w4]) = v;
            }
            __syncthreads();

#pragma unroll 4
            for (int cc = 0; cc < 32; ++cc) {
                int c = cbase + cc;
                const float* hrow = &hs[c*HSTR + wb];
                float  hm1 = hrow[3];                                    // h[wb-1]
                float4 h03 = *reinterpret_cast<const float4*>(hrow + 4); // h[wb..wb+3]
                float  h4  = hrow[8];                                    // h[wb+4]
                float hv[6] = {hm1, h03.x, h03.y, h03.z, h03.w, h4};
                u64 hp[6];
#pragma unroll
                for (int t = 0; t < 6; ++t) PACK2(hp[t], hv[t], hv[t]);
                // weights for 4 consecutive o-pairs: 16+8 consecutive floats
                const float* wp = &wk01[(c*32 + prb)*4];
                ulonglong2 wa = *reinterpret_cast<const ulonglong2*>(wp);
                ulonglong2 wb2 = *reinterpret_cast<const ulonglong2*>(wp + 8);
                const float* w2p = &wk2[(c*32 + prb)*2];
                ulonglong2 w2a = *reinterpret_cast<const ulonglong2*>(w2p);
                ulonglong2 w2b = *reinterpret_cast<const ulonglong2*>(w2p + 4);
                u64 w01k0[4] = {wa.x, wa.y, wb2.x, wb2.y};   // {k0(p),k1(p)} interleaved
                // layout: wp = [p0:{k0,k1}, p1:{k0,k1}, p2:{k0,k1}, p3:{k0,k1}]
                // wa.x=p0k0k1? NO: wk01 per pair = 4 floats {k0e,k0o,k1e,k1o}
                // so pair p occupies floats [4p..4p+4): wa = pairs 0 (k0,k1), etc.
                u64 wk0[4], wk1[4], w2v[4];
                wk0[0] = wa.x;  wk1[0] = wa.y;
                wk0[1] = *reinterpret_cast<const u64*>(wp + 4);
                wk1[1] = *reinterpret_cast<const u64*>(wp + 6);
                wk0[2] = wb2.x; wk1[2] = wb2.y;
                wk0[3] = *reinterpret_cast<const u64*>(wp + 12);
                wk1[3] = *reinterpret_cast<const u64*>(wp + 14);
                w2v[0] = w2a.x; w2v[1] = w2a.y; w2v[2] = w2b.x; w2v[3] = w2b.y;
                (void)w01k0;
#pragma unroll
                for (int p = 0; p < 4; ++p) {
#pragma unroll
                    for (int i = 0; i < 4; ++i) {
                        FMA2(acc[p][i], wk0[p], hp[i],   acc[p][i]);
                        FMA2(acc[p][i], wk1[p], hp[i+1], acc[p][i]);
                        FMA2(acc[p][i], w2v[p], hp[i+2], acc[p][i]);
                    }
                }
            }
        }

        // stage partial z_ss into zbuf[ks][w][o_local] (o pairs contiguous)
        {
            float* zb = zbuf + ks*ZB1;
#pragma unroll
            for (int p = 0; p < 4; ++p)
#pragma unroll
                for (int i = 0; i < 4; ++i)
                    *reinterpret_cast<u64*>(&zb[(wb + i)*66 + (prb + p)*2]) = acc[p][i];
        }
        __syncthreads();

        // gates for (ch = chg, w = wg, wg+1); z = sum of 4 K-partials
        float2 hres;
#pragma unroll
        for (int j = 0; j < 2; ++j) {
            int w = wg + j;
            float zs[4];
#pragma unroll
            for (int g = 0; g < 4; ++g) {
                float s = zbuf[w*66 + g*16 + cl];
#pragma unroll
                for (int q = 1; q < 4; ++q)
                    s += zbuf[q*ZB1 + w*66 + g*16 + cl];
                zs[g] = s;
            }
            float zi = zs[0] + sbv[0] + (j ? zv[0].y : zv[0].x);
            float zf = zs[1] + sbv[1] + (j ? zv[1].y : zv[1].x);
            float zo = zs[2] + sbv[2] + (j ? zv[2].y : zv[2].x);
            float zg = zs[3] + sbv[3] + (j ? zv[3].y : zv[3].x);
            float ig = 1.f / (1.f + __expf(-zi));
            float fg = 1.f / (1.f + __expf(-zf));
            float og = 1.f / (1.f + __expf(-zo));
            float gg = tanhf(zg);
            float cn = fg*cst[j] + ig*gg;
            cst[j] = cn;
            (&hres.x)[j] = og * tanhf(cn);
        }
        *reinterpret_cast<float2*>(&out[(((size_t)b*HID + chg)*Hh + r)*Ww + wg]) = hres;

        if (r < Hh - 1) {
            // publish h_r, then release-arrive on the per-b counter
            __stcg(reinterpret_cast<float2*>(
                &g_hbuf[r & 1][(b*HID + chg)*Ww + wg]), hres);
            __syncthreads();               // all stcg done before the release
            if (tid == 0) red_rel_gpu(cnt, 1u);
        }
    }
}

// ---------------------------------------------------------------------------
extern "C" void kernel_launch(void* const* d_in, const int* in_sizes, int n_in,
                              void* d_out, int out_size) {
    const float* x   = (const float*)d_in[0];
    const float* Wis = (const float*)d_in[1];
    const float* bis = (const float*)d_in[2];
    const float* Wss = (const float*)d_in[3];
    const float* bss = (const float*)d_in[4];
    float* out = (float*)d_out;

    const int SMEM_A = (16384 + 8192)*sizeof(float);                    //  98304
    const int SMEM_P = (16384 + 8192 + HS1 + 4*ZB1)*sizeof(float);      // 202752
    cudaFuncSetAttribute(kA_zis,  cudaFuncAttributeMaxDynamicSharedMemorySize, SMEM_A);
    cudaFuncSetAttribute(kP_rows, cudaFuncAttributeMaxDynamicSharedMemorySize, SMEM_P);

    init_kernel<<<1, 512>>>();

    dim3 gA(Bb*Hh, OC/64);
    kA_zis<<<gA, 512, SMEM_A>>>(x, Wis, bis);

    kP_rows<<<NCTA, 512, SMEM_P>>>(Wss, bss, out);
}

// round 12
// speedup vs baseline: 1.1908x; 1.0309x over previous
#include <cuda_runtime.h>
#include <cuda_bf16.h>
#include <stdint.h>
#include <math.h>

#define Bb   16
#define Cc   128
#define Hh   64
#define Ww   64
#define HID  128
#define OC   512
#define NCTA 128   // 16 b x 8 hid-blocks

typedef unsigned long long u64;

// Scratch (device globals: allocation-free per harness rules)
__device__ float    g_zis[(size_t)Bb*OC*Hh*Ww];   // [b, o, h, w]
__device__ float    g_hbuf[2][Bb*HID*Ww];         // double-buffered hidden state
__device__ unsigned g_cnt[16*32];                 // per-batch barrier counters

// ---- fp32x2 helpers (kA) ---------------------------------------------------
#define PACK2(d, lo, hi) asm("mov.b64 %0, {%1,%2};" : "=l"(d) : "f"(lo), "f"(hi))
#define FMA2(d, a, b, c) asm("fma.rn.f32x2 %0, %1, %2, %3;" : "=l"(d) : "l"(a), "l"(b), "l"(c))
#define UNPK2(lo, hi, s) asm("mov.b64 {%0,%1}, %2;" : "=f"(lo), "=f"(hi) : "l"(s))

__device__ __forceinline__ unsigned ld_acq_gpu(const unsigned* p) {
    unsigned v;
    asm volatile("ld.global.acquire.gpu.u32 %0, [%1];" : "=r"(v) : "l"(p) : "memory");
    return v;
}
__device__ __forceinline__ void red_rel_gpu(unsigned* p, unsigned v) {
    asm volatile("red.release.gpu.global.add.u32 [%0], %1;" :: "l"(p), "r"(v) : "memory");
}
__device__ __forceinline__ uint32_t smem_u32(const void* p) {
    uint32_t a;
    asm("{ .reg .u64 t; cvta.to.shared.u64 t, %1; cvt.u32.u64 %0, t; }" : "=r"(a) : "l"(p));
    return a;
}

// ---- legacy tensor-core helpers (sm_80+ PTX, no arch-suffix features) ------
__device__ __forceinline__ void ldsm_x4(uint32_t* r, uint32_t addr) {
    asm volatile("ldmatrix.sync.aligned.m8n8.x4.shared.b16 {%0,%1,%2,%3}, [%4];"
                 : "=r"(r[0]), "=r"(r[1]), "=r"(r[2]), "=r"(r[3]) : "r"(addr));
}
__device__ __forceinline__ void mma_bf16(float* d, const uint32_t* a, const uint32_t* b) {
    asm volatile("mma.sync.aligned.m16n8k16.row.col.f32.bf16.bf16.f32 "
                 "{%0,%1,%2,%3}, {%4,%5,%6,%7}, {%8,%9}, {%0,%1,%2,%3};"
                 : "+f"(d[0]), "+f"(d[1]), "+f"(d[2]), "+f"(d[3])
                 : "r"(a[0]), "r"(a[1]), "r"(a[2]), "r"(a[3]), "r"(b[0]), "r"(b[1]));
}

// swizzled byte address inside an A/B tile: row stride 768B (384 bf16),
// 16B chunks XOR'ed by (row & 7)  ->  ldmatrix conflict-free
__device__ __forceinline__ uint32_t swaddr(int row, int k) {
    return (uint32_t)(row*768 + ((((k >> 3) ^ (row & 7)) << 4) | ((k & 7) << 1)));
}

// smem layout (bytes) for kP
#define A_OFF    0          // A [128][384] bf16 swizzled          98304
#define BHI_OFF  98304      // Bhi [64][384] bf16 swizzled          49152
#define BLO_OFF  147456     // Blo                                  49152
#define HS_OFF   196608     // hs fp32 [128][68] (aliased: zbuf [128][66])
#define SMEM_P   231424

// ---------------------------------------------------------------------------
__global__ void init_kernel() {
    int i = threadIdx.x;
    if (i < 16*32) g_cnt[i] = 0u;
}

// ---------------------------------------------------------------------------
// Phase 1: masked input-to-state conv (unchanged from R8 — near fp32 floor)
__global__ void __launch_bounds__(512)
kA_zis(const float* __restrict__ x,
       const float* __restrict__ Wis,
       const float* __restrict__ bis) {
    extern __shared__ float sm[];
    float* wt = sm;               // [c][32][4]
    float* xs = sm + 16384;       // [c][64]

    int b  = blockIdx.x >> 6;
    int h  = blockIdx.x & 63;
    int o0 = blockIdx.y * 64;
    int tid = threadIdx.x;

    for (int idx = tid; idx < 8192; idx += 512)
        xs[idx] = x[(((size_t)b*Cc + (idx >> 6))*Hh + h)*Ww + (idx & 63)];

    {
        const float* wsrc = Wis + (size_t)o0 * (Cc*3);
        for (int idx = tid; idx < 64*Cc*3; idx += 512) {
            float v = wsrc[idx];
            int ol  = idx / (Cc*3);
            int rem = idx - ol*(Cc*3);
            int c   = rem / 3;
            int k   = rem - c*3;
            if (k < 2) wt[(c*32 + (ol >> 1))*4 + k*2 + (ol & 1)] = v;
        }
    }
    __syncthreads();

    int tx  = tid & 15;
    int typ = tid >> 4;
    int wb  = tx * 4;

    u64 acc[4] = {0ull, 0ull, 0ull, 0ull};

#pragma unroll 2
    for (int c = 0; c < 128; ++c) {
        const float* xr = &xs[c*64 + wb];
        float4 xv = *reinterpret_cast<const float4*>(xr);
        float xm1 = (wb == 0) ? 0.f : xr[-1];
        float hv[5] = {xm1, xv.x, xv.y, xv.z, xv.w};
        u64 hp[5];
#pragma unroll
        for (int t = 0; t < 5; ++t) PACK2(hp[t], hv[t], hv[t]);
        ulonglong2 w01 = *reinterpret_cast<const ulonglong2*>(&wt[(c*32 + typ)*4]);
#pragma unroll
        for (int i = 0; i < 4; ++i) {
            FMA2(acc[i], w01.x, hp[i],   acc[i]);
            FMA2(acc[i], w01.y, hp[i+1], acc[i]);
        }
    }

    float lo[4], hi[4];
#pragma unroll
    for (int i = 0; i < 4; ++i) UNPK2(lo[i], hi[i], acc[i]);
    int oA = o0 + typ*2;
    float bA = bis[oA], bB = bis[oA+1];
    float4 rA = {lo[0]+bA, lo[1]+bA, lo[2]+bA, lo[3]+bA};
    float4 rB = {hi[0]+bB, hi[1]+bB, hi[2]+bB, hi[3]+bB};
    *reinterpret_cast<float4*>(&g_zis[(((size_t)b*OC + oA  )*Hh + h)*Ww + wb]) = rA;
    *reinterpret_cast<float4*>(&g_zis[(((size_t)b*OC + oA+1)*Hh + h)*Ww + wb]) = rB;
}

// ---------------------------------------------------------------------------
// Phase 2: persistent recurrence, tensor-core (mma.sync bf16, split precision).
// CTA (b, hb): o_local ol = g*16+l -> o = g*128 + hb*16 + l.
// A[128][384]: row 2ol = Whi(ol), row 2ol+1 = Wlo(ol). Two passes (Bhi, Blo)
// accumulate D[128][64]; z[ol][w] = D[2ol][w] + D[2ol+1][w].
__global__ void __launch_bounds__(512, 1)
kP_rows(const float* __restrict__ Wss,
        const float* __restrict__ bss,
        float* __restrict__ out) {
    extern __shared__ char smc[];
    float* hs   = reinterpret_cast<float*>(smc + HS_OFF);   // [128][68]
    float* zbuf = reinterpret_cast<float*>(smc + HS_OFF);   // alias [128][66]
    uint32_t smem_base = smem_u32(smc);

    int b   = blockIdx.x >> 3;
    int hb  = blockIdx.x & 7;
    int tid = threadIdx.x;
    int wid = tid >> 5;
    int lane = tid & 31;
    unsigned* cnt = &g_cnt[b*32];

    // Build A (weights split bf16, swizzled) once
    for (int idx = tid; idx < 64*384; idx += 512) {
        int ol  = idx / 384;
        int rem = idx - ol*384;
        int o   = (ol >> 4)*128 + hb*16 + (ol & 15);
        float v = Wss[(size_t)o*384 + rem];
        __nv_bfloat16 vh = __float2bfloat16_rn(v);
        __nv_bfloat16 vl = __float2bfloat16_rn(v - __bfloat162float(vh));
        *reinterpret_cast<__nv_bfloat16*>(smc + A_OFF + swaddr(2*ol,     rem)) = vh;
        *reinterpret_cast<__nv_bfloat16*>(smc + A_OFF + swaddr(2*ol + 1, rem)) = vl;
    }

    // MMA warp mapping: warp = (mt 0..7, nh 0..1)
    int mt = wid & 7, nh = wid >> 3;
    int m0 = mt*16, n0 = nh*32;
    int sw   = lane & 7;                       // xor key (rows ≡ lane low bits mod 8)
    int csa  = lane >> 4;                      // A k-chunk select
    int bm   = lane >> 3;                      // B x4 quadrant
    int csb  = bm & 1;                         // B k-chunk select
    int rbo  = (bm >> 1)*8 + (lane & 7);       // B row offset within 16-row half
    uint32_t a_row  = smem_base + A_OFF + (uint32_t)(m0 + (lane & 15))*768;
    uint32_t b_row0 = (uint32_t)(n0 + rbo)*768;        // n-half 0 (nt 0,1)
    uint32_t b_row1 = (uint32_t)(n0 + 16 + rbo)*768;   // n-half 1 (nt 2,3)

    // gate-phase mapping (R8): cl channel-local, 2 consecutive w per thread
    int cl  = tid >> 5;
    int wg  = (tid & 31) * 2;
    int chg = hb*16 + cl;
    float sbv[4];
#pragma unroll
    for (int g = 0; g < 4; ++g) sbv[g] = bss[g*128 + chg];
    float cst[2] = {0.f, 0.f};

    // B-build mapping: row bw = tid&63, c segment = tid>>6 (16 c's)
    int bw  = tid & 63;
    int seg = tid >> 6;

    const float* zisb = g_zis + (size_t)b*OC*Hh*Ww;
    __syncthreads();

    for (int r = 0; r < Hh; ++r) {
        // prefetch z_is for gates (overlaps barrier poll)
        float2 zv[4];
#pragma unroll
        for (int g = 0; g < 4; ++g)
            zv[g] = *reinterpret_cast<const float2*>(
                &zisb[(((size_t)(g*128 + chg))*Hh + r)*Ww + wg]);

        float acc[4][4];
#pragma unroll
        for (int nt = 0; nt < 4; ++nt)
#pragma unroll
            for (int i = 0; i < 4; ++i) acc[nt][i] = 0.f;

        if (r > 0) {
            // wait for all 8 CTAs of this b to have published row r-1
            if (tid == 0) {
                unsigned target = 8u * (unsigned)r;
                while (ld_acq_gpu(cnt) < target) __nanosleep(32);
            }
            __syncthreads();
            // reload h into hs [128][68]
            {
                const float4* hsrc = reinterpret_cast<const float4*>(
                    g_hbuf[(r-1) & 1] + b*HID*Ww);
#pragma unroll
                for (int it = 0; it < 4; ++it) {
                    int j = tid + it*512;
                    int c = j >> 4, w4 = (j & 15) * 4;
                    float4 v = __ldcg(&hsrc[j]);
                    *reinterpret_cast<float4*>(&hs[c*68 + w4]) = v;
                }
            }
            __syncthreads();

            // build Bhi/Blo: B[bw][c*3+kk] = h[c][bw+kk-1] split into bf16 hi/lo
#pragma unroll 2
            for (int i = 0; i < 8; ++i) {
                int cA = seg*16 + 2*i;
                const float* hA = &hs[cA*68 + bw];
                const float* hB = &hs[(cA+1)*68 + bw];
                float vals[6];
                vals[0] = (bw > 0)  ? hA[-1] : 0.f;
                vals[1] = hA[0];
                vals[2] = (bw < 63) ? hA[1]  : 0.f;
                vals[3] = (bw > 0)  ? hB[-1] : 0.f;
                vals[4] = hB[0];
                vals[5] = (bw < 63) ? hB[1]  : 0.f;
                int kb = cA*3;
#pragma unroll
                for (int j = 0; j < 3; ++j) {
                    float v0 = vals[2*j], v1 = vals[2*j+1];
                    __nv_bfloat16 h0 = __float2bfloat16_rn(v0);
                    __nv_bfloat16 h1 = __float2bfloat16_rn(v1);
                    __nv_bfloat16 l0 = __float2bfloat16_rn(v0 - __bfloat162float(h0));
                    __nv_bfloat16 l1 = __float2bfloat16_rn(v1 - __bfloat162float(h1));
                    uint32_t phi = (uint32_t)__bfloat16_as_ushort(h0) |
                                   ((uint32_t)__bfloat16_as_ushort(h1) << 16);
                    uint32_t plo = (uint32_t)__bfloat16_as_ushort(l0) |
                                   ((uint32_t)__bfloat16_as_ushort(l1) << 16);
                    uint32_t off = swaddr(bw, kb + 2*j);
                    *reinterpret_cast<uint32_t*>(smc + BHI_OFF + off) = phi;
                    *reinterpret_cast<uint32_t*>(smc + BLO_OFF + off) = plo;
                }
            }
            __syncthreads();

            // tensor GEMM: 2 passes x 24 k-tiles, acc in registers
#pragma unroll 1
            for (int pass = 0; pass < 2; ++pass) {
                uint32_t Bbase = smem_base + (pass ? BLO_OFF : BHI_OFF);
#pragma unroll 4
                for (int kt = 0; kt < 24; ++kt) {
                    uint32_t ca = (uint32_t)(((2*kt + csa) ^ sw) << 4);
                    uint32_t cb = (uint32_t)(((2*kt + csb) ^ sw) << 4);
                    uint32_t a[4], b0[4], b1[4];
                    ldsm_x4(a,  a_row + ca);
                    ldsm_x4(b0, Bbase + b_row0 + cb);
                    ldsm_x4(b1, Bbase + b_row1 + cb);
                    mma_bf16(acc[0], a, b0);
                    mma_bf16(acc[1], a, b0 + 2);
                    mma_bf16(acc[2], a, b1);
                    mma_bf16(acc[3], a, b1 + 2);
                }
            }

            // epilogue: acc -> zbuf [128][66] (overwrites hs; B-build done)
            {
                int er = lane >> 2, ec = (lane & 3)*2;
#pragma unroll
                for (int nt = 0; nt < 4; ++nt) {
                    int col = n0 + nt*8 + ec;
                    *reinterpret_cast<float2*>(&zbuf[(m0 + er)*66 + col]) =
                        make_float2(acc[nt][0], acc[nt][1]);
                    *reinterpret_cast<float2*>(&zbuf[(m0 + er + 8)*66 + col]) =
                        make_float2(acc[nt][2], acc[nt][3]);
                }
            }
        }
        __syncthreads();

        // gates: z_ss[ol][w] = D[2ol][w] + D[2ol+1][w]
        float2 hres;
#pragma unroll
        for (int j = 0; j < 2; ++j) {
            int w = wg + j;
            float zs[4];
#pragma unroll
            for (int g = 0; g < 4; ++g) {
                if (r > 0) {
                    int rowA = (32*g + 2*cl);
                    zs[g] = zbuf[rowA*66 + w] + zbuf[(rowA + 1)*66 + w];
                } else zs[g] = 0.f;
            }
            float zi = zs[0] + sbv[0] + (j ? zv[0].y : zv[0].x);
            float zf = zs[1] + sbv[1] + (j ? zv[1].y : zv[1].x);
            float zo = zs[2] + sbv[2] + (j ? zv[2].y : zv[2].x);
            float zg = zs[3] + sbv[3] + (j ? zv[3].y : zv[3].x);
            float ig = 1.f / (1.f + __expf(-zi));
            float fg = 1.f / (1.f + __expf(-zf));
            float og = 1.f / (1.f + __expf(-zo));
            float gg = tanhf(zg);
            float cn = fg*cst[j] + ig*gg;
            cst[j] = cn;
            (&hres.x)[j] = og * tanhf(cn);
        }
        *reinterpret_cast<float2*>(&out[(((size_t)b*HID + chg)*Hh + r)*Ww + wg]) = hres;

        if (r < Hh - 1) {
            __stcg(reinterpret_cast<float2*>(
                &g_hbuf[r & 1][(b*HID + chg)*Ww + wg]), hres);
            __syncthreads();
            if (tid == 0) red_rel_gpu(cnt, 1u);
        }
    }
}

// ---------------------------------------------------------------------------
extern "C" void kernel_launch(void* const* d_in, const int* in_sizes, int n_in,
                              void* d_out, int out_size) {
    const float* x   = (const float*)d_in[0];
    const float* Wis = (const float*)d_in[1];
    const float* bis = (const float*)d_in[2];
    const float* Wss = (const float*)d_in[3];
    const float* bss = (const float*)d_in[4];
    float* out = (float*)d_out;

    const int SMEM_A = (16384 + 8192)*sizeof(float);
    cudaFuncSetAttribute(kA_zis,  cudaFuncAttributeMaxDynamicSharedMemorySize, SMEM_A);
    cudaFuncSetAttribute(kP_rows, cudaFuncAttributeMaxDynamicSharedMemorySize, SMEM_P);

    init_kernel<<<1, 512>>>();

    dim3 gA(Bb*Hh, OC/64);
    kA_zis<<<gA, 512, SMEM_A>>>(x, Wis, bis);

    kP_rows<<<NCTA, 512, SMEM_P>>>(Wss, bss, out);
}

// round 13
// speedup vs baseline: 1.4711x; 1.2354x over previous
#include <cuda_runtime.h>
#include <cuda_bf16.h>
#include <cuda_fp16.h>
#include <stdint.h>
#include <math.h>

#define Bb   16
#define Cc   128
#define Hh   64
#define Ww   64
#define HID  128
#define OC   512
#define NCTA 128   // 16 b x 8 hid-blocks

typedef unsigned long long u64;

// Scratch (device globals: allocation-free per harness rules)
__device__ float    g_zis[(size_t)Bb*OC*Hh*Ww];   // [b, o, h, w]
__device__ float    g_hbuf[2][Bb*HID*Ww];         // double-buffered hidden state
__device__ unsigned g_cnt[32*32];                 // per-batch barrier counters
                                                  // [b*32]: row counter, [(16+b)*32]: reset rendezvous

__device__ __forceinline__ unsigned ld_acq_gpu(const unsigned* p) {
    unsigned v;
    asm volatile("ld.global.acquire.gpu.u32 %0, [%1];" : "=r"(v) : "l"(p) : "memory");
    return v;
}
__device__ __forceinline__ void red_rel_gpu(unsigned* p, unsigned v) {
    asm volatile("red.release.gpu.global.add.u32 [%0], %1;" :: "l"(p), "r"(v) : "memory");
}
__device__ __forceinline__ void st_rel_gpu(unsigned* p, unsigned v) {
    asm volatile("st.global.release.gpu.u32 [%0], %1;" :: "l"(p), "r"(v) : "memory");
}
__device__ __forceinline__ uint32_t smem_u32(const void* p) {
    uint32_t a;
    asm("{ .reg .u64 t; cvta.to.shared.u64 t, %1; cvt.u32.u64 %0, t; }" : "=r"(a) : "l"(p));
    return a;
}

// ---- legacy tensor-core helpers (sm_80+ PTX, no arch-suffix features) ------
__device__ __forceinline__ void ldsm_x4(uint32_t* r, uint32_t addr) {
    asm volatile("ldmatrix.sync.aligned.m8n8.x4.shared.b16 {%0,%1,%2,%3}, [%4];"
                 : "=r"(r[0]), "=r"(r[1]), "=r"(r[2]), "=r"(r[3]) : "r"(addr));
}
__device__ __forceinline__ void mma_bf16(float* d, const uint32_t* a, const uint32_t* b) {
    asm volatile("mma.sync.aligned.m16n8k16.row.col.f32.bf16.bf16.f32 "
                 "{%0,%1,%2,%3}, {%4,%5,%6,%7}, {%8,%9}, {%0,%1,%2,%3};"
                 : "+f"(d[0]), "+f"(d[1]), "+f"(d[2]), "+f"(d[3])
                 : "r"(a[0]), "r"(a[1]), "r"(a[2]), "r"(a[3]), "r"(b[0]), "r"(b[1]));
}
__device__ __forceinline__ void mma_fp16(float* d, const uint32_t* a, const uint32_t* b) {
    asm volatile("mma.sync.aligned.m16n8k16.row.col.f32.f16.f16.f32 "
                 "{%0,%1,%2,%3}, {%4,%5,%6,%7}, {%8,%9}, {%0,%1,%2,%3};"
                 : "+f"(d[0]), "+f"(d[1]), "+f"(d[2]), "+f"(d[3])
                 : "r"(a[0]), "r"(a[1]), "r"(a[2]), "r"(a[3]), "r"(b[0]), "r"(b[1]));
}

// ---------------------------------------------------------------------------
// Phase 1: masked input-to-state conv on TENSOR CORES (fp16 two-term split).
// z = W*X with W ~ Whi+Wlo (fp16): A = [Whi | Wlo] (M=128 o, K-concat 512),
// pass1: A x Xhi (virtual kt 0..31, B kt = kt&15); pass2: Whi x Xlo (kt 32..47).
// Omits only Wlo*Xlo (~2^-22). K = 2 taps x 128 c (tap2 masked away).
#define KA_A_OFF  0          // fp16 A [128][512] swizzled        131072
#define KA_BH_OFF 131072     // fp16 Xhi [64][256] swizzled        32768
#define KA_BL_OFF 163840     // fp16 Xlo                           32768
#define KA_Z_OFF  196608     // fp32 zbuf [128][68] / xs [128][64] 34816
#define SMEM_KA   231424

__device__ __forceinline__ uint32_t swA(int row, int k) {   // row stride 1024B
    return (uint32_t)(row*1024 + ((((k >> 3) ^ (row & 7)) << 4) | ((k & 7) << 1)));
}
__device__ __forceinline__ uint32_t swBx(int row, int k) {  // row stride 512B
    return (uint32_t)(row*512 + ((((k >> 3) ^ (row & 7)) << 4) | ((k & 7) << 1)));
}

__global__ void __launch_bounds__(512, 1)
kA_zis(const float* __restrict__ x,
       const float* __restrict__ Wis,
       const float* __restrict__ bis) {
    extern __shared__ char smc[];
    float* xs = reinterpret_cast<float*>(smc + KA_Z_OFF);   // [128][64]
    float* zb = reinterpret_cast<float*>(smc + KA_Z_OFF);   // [128][68] after MMA
    uint32_t sb = smem_u32(smc);

    int b  = blockIdx.x >> 6;
    int h  = blockIdx.x & 63;
    int o0 = blockIdx.y * 128;
    int tid = threadIdx.x, wid = tid >> 5, lane = tid & 31;

    // stage x row [128 c][64 w] (coalesced)
    for (int idx = tid; idx < 8192; idx += 512)
        xs[idx] = x[(((size_t)b*Cc + (idx >> 6))*Hh + h)*Ww + (idx & 63)];

    // build A: A[ol][k] (k<256: Whi at k, Wlo at k+256); k = 2c+t, taps t=0,1
    for (int idx = tid; idx < 128*256; idx += 512) {
        int ol = idx >> 8, k = idx & 255;
        int c = k >> 1, t = k & 1;
        float v = Wis[(size_t)(o0 + ol)*384 + c*3 + t];
        __half vh = __float2half_rn(v);
        __half vl = __float2half_rn(v - __half2float(vh));
        *reinterpret_cast<__half*>(smc + KA_A_OFF + swA(ol, k))       = vh;
        *reinterpret_cast<__half*>(smc + KA_A_OFF + swA(ol, k + 256)) = vl;
    }
    __syncthreads();

    // build B: B[w][2c] = x[c][w-1], B[w][2c+1] = x[c][w], split fp16 hi/lo
    {
        int bw = tid & 63, seg = tid >> 6;
#pragma unroll 4
        for (int i = 0; i < 16; ++i) {
            int c = seg*16 + i;
            float x0 = xs[c*64 + bw];
            float xm = bw ? xs[c*64 + bw - 1] : 0.f;
            __half h0 = __float2half_rn(xm), h1 = __float2half_rn(x0);
            __half l0 = __float2half_rn(xm - __half2float(h0));
            __half l1 = __float2half_rn(x0 - __half2float(h1));
            uint32_t phi = (uint32_t)__half_as_ushort(h0) | ((uint32_t)__half_as_ushort(h1) << 16);
            uint32_t plo = (uint32_t)__half_as_ushort(l0) | ((uint32_t)__half_as_ushort(l1) << 16);
            uint32_t off = swBx(bw, 2*c);
            *reinterpret_cast<uint32_t*>(smc + KA_BH_OFF + off) = phi;
            *reinterpret_cast<uint32_t*>(smc + KA_BL_OFF + off) = plo;
        }
    }
    __syncthreads();

    // MMA: warps (mt 0..7, nh 0..1); per kt: 1 A-x4 + 2 B-x4 + 4 mma
    int mt = wid & 7, nh = wid >> 3;
    int m0 = mt*16, n0 = nh*32;
    int sw8 = lane & 7;
    int csa = lane >> 4;
    int bm  = lane >> 3, csb = bm & 1;
    int rbo = (bm >> 1)*8 + (lane & 7);
    uint32_t a_row = sb + KA_A_OFF + (uint32_t)(m0 + (lane & 15))*1024;
    uint32_t b_r0  = (uint32_t)(n0 + rbo)*512;
    uint32_t b_r1  = (uint32_t)(n0 + 16 + rbo)*512;

    float acc[4][4];
#pragma unroll
    for (int nt = 0; nt < 4; ++nt)
#pragma unroll
        for (int i = 0; i < 4; ++i) acc[nt][i] = 0.f;

#pragma unroll 4
    for (int kt = 0; kt < 48; ++kt) {
        int ktA = (kt < 32) ? kt : (kt - 32);
        int ktB = (kt < 32) ? (kt & 15) : (kt - 32);
        uint32_t Bbase = sb + ((kt < 32) ? KA_BH_OFF : KA_BL_OFF);
        uint32_t ca = (uint32_t)(((2*ktA + csa) ^ sw8) << 4);
        uint32_t cb = (uint32_t)(((2*ktB + csb) ^ sw8) << 4);
        uint32_t a[4], b0[4], b1[4];
        ldsm_x4(a,  a_row + ca);
        ldsm_x4(b0, Bbase + b_r0 + cb);
        ldsm_x4(b1, Bbase + b_r1 + cb);
        mma_fp16(acc[0], a, b0);
        mma_fp16(acc[1], a, b0 + 2);
        mma_fp16(acc[2], a, b1);
        mma_fp16(acc[3], a, b1 + 2);
    }

    // stage D to zbuf [128][68] (xs dead; MMA reads only A/B regions)
    {
        int er = lane >> 2, ec = (lane & 3)*2;
#pragma unroll
        for (int nt = 0; nt < 4; ++nt) {
            int col = n0 + nt*8 + ec;
            *reinterpret_cast<float2*>(&zb[(m0 + er)*68 + col]) =
                make_float2(acc[nt][0], acc[nt][1]);
            *reinterpret_cast<float2*>(&zb[(m0 + er + 8)*68 + col]) =
                make_float2(acc[nt][2], acc[nt][3]);
        }
    }
    __syncthreads();

    // write z_is + bias (coalesced float4)
    {
        int ol = tid >> 2, ws = (tid & 3)*16;
        float bv = bis[o0 + ol];
        float* dst = &g_zis[(((size_t)b*OC + o0 + ol)*Hh + h)*Ww + ws];
#pragma unroll
        for (int j = 0; j < 16; j += 4) {
            float4 v = *reinterpret_cast<const float4*>(&zb[ol*68 + ws + j]);
            v.x += bv; v.y += bv; v.z += bv; v.w += bv;
            *reinterpret_cast<float4*>(dst + j) = v;
        }
    }
}

// ---------------------------------------------------------------------------
// Phase 2: persistent recurrence, tensor-core (mma.sync bf16, split precision).
// Identical to R12 except self-resetting counters (init kernel removed).
#define A_OFF    0          // A [128][384] bf16 swizzled          98304
#define BHI_OFF  98304      // Bhi [64][384] bf16 swizzled          49152
#define BLO_OFF  147456     // Blo                                  49152
#define HS_OFF   196608     // hs fp32 [128][68] (aliased: zbuf [128][66])
#define SMEM_P   231424

__device__ __forceinline__ uint32_t swaddr(int row, int k) {   // row stride 768B
    return (uint32_t)(row*768 + ((((k >> 3) ^ (row & 7)) << 4) | ((k & 7) << 1)));
}

__global__ void __launch_bounds__(512, 1)
kP_rows(const float* __restrict__ Wss,
        const float* __restrict__ bss,
        float* __restrict__ out) {
    extern __shared__ char smc[];
    float* hs   = reinterpret_cast<float*>(smc + HS_OFF);   // [128][68]
    float* zbuf = reinterpret_cast<float*>(smc + HS_OFF);   // alias [128][66]
    uint32_t smem_base = smem_u32(smc);

    int b   = blockIdx.x >> 3;
    int hb  = blockIdx.x & 7;
    int tid = threadIdx.x;
    int wid = tid >> 5;
    int lane = tid & 31;
    unsigned* cnt  = &g_cnt[b*32];
    unsigned* cnt2 = &g_cnt[(16 + b)*32];

    // Build A (weights split bf16, swizzled) once
    for (int idx = tid; idx < 64*384; idx += 512) {
        int ol  = idx / 384;
        int rem = idx - ol*384;
        int o   = (ol >> 4)*128 + hb*16 + (ol & 15);
        float v = Wss[(size_t)o*384 + rem];
        __nv_bfloat16 vh = __float2bfloat16_rn(v);
        __nv_bfloat16 vl = __float2bfloat16_rn(v - __bfloat162float(vh));
        *reinterpret_cast<__nv_bfloat16*>(smc + A_OFF + swaddr(2*ol,     rem)) = vh;
        *reinterpret_cast<__nv_bfloat16*>(smc + A_OFF + swaddr(2*ol + 1, rem)) = vl;
    }

    // MMA warp mapping: warp = (mt 0..7, nh 0..1)
    int mt = wid & 7, nh = wid >> 3;
    int m0 = mt*16, n0 = nh*32;
    int sw   = lane & 7;
    int csa  = lane >> 4;
    int bm   = lane >> 3;
    int csb  = bm & 1;
    int rbo  = (bm >> 1)*8 + (lane & 7);
    uint32_t a_row  = smem_base + A_OFF + (uint32_t)(m0 + (lane & 15))*768;
    uint32_t b_row0 = (uint32_t)(n0 + rbo)*768;
    uint32_t b_row1 = (uint32_t)(n0 + 16 + rbo)*768;

    // gate-phase mapping: cl channel-local, 2 consecutive w per thread
    int cl  = tid >> 5;
    int wg  = (tid & 31) * 2;
    int chg = hb*16 + cl;
    float sbv[4];
#pragma unroll
    for (int g = 0; g < 4; ++g) sbv[g] = bss[g*128 + chg];
    float cst[2] = {0.f, 0.f};

    // B-build mapping: row bw = tid&63, c segment = tid>>6 (16 c's)
    int bw  = tid & 63;
    int seg = tid >> 6;

    const float* zisb = g_zis + (size_t)b*OC*Hh*Ww;
    __syncthreads();

    for (int r = 0; r < Hh; ++r) {
        // prefetch z_is for gates (overlaps barrier poll)
        float2 zv[4];
#pragma unroll
        for (int g = 0; g < 4; ++g)
            zv[g] = *reinterpret_cast<const float2*>(
                &zisb[(((size_t)(g*128 + chg))*Hh + r)*Ww + wg]);

        float acc[4][4];
#pragma unroll
        for (int nt = 0; nt < 4; ++nt)
#pragma unroll
            for (int i = 0; i < 4; ++i) acc[nt][i] = 0.f;

        if (r > 0) {
            if (tid == 0) {
                unsigned target = 8u * (unsigned)r;
                while (ld_acq_gpu(cnt) < target) __nanosleep(32);
            }
            __syncthreads();
            {
                const float4* hsrc = reinterpret_cast<const float4*>(
                    g_hbuf[(r-1) & 1] + b*HID*Ww);
#pragma unroll
                for (int it = 0; it < 4; ++it) {
                    int j = tid + it*512;
                    int c = j >> 4, w4 = (j & 15) * 4;
                    float4 v = __ldcg(&hsrc[j]);
                    *reinterpret_cast<float4*>(&hs[c*68 + w4]) = v;
                }
            }
            __syncthreads();

            // build Bhi/Blo: B[bw][c*3+kk] = h[c][bw+kk-1] split into bf16 hi/lo
#pragma unroll 2
            for (int i = 0; i < 8; ++i) {
                int cA = seg*16 + 2*i;
                const float* hA = &hs[cA*68 + bw];
                const float* hB = &hs[(cA+1)*68 + bw];
                float vals[6];
                vals[0] = (bw > 0)  ? hA[-1] : 0.f;
                vals[1] = hA[0];
                vals[2] = (bw < 63) ? hA[1]  : 0.f;
                vals[3] = (bw > 0)  ? hB[-1] : 0.f;
                vals[4] = hB[0];
                vals[5] = (bw < 63) ? hB[1]  : 0.f;
                int kb = cA*3;
#pragma unroll
                for (int j = 0; j < 3; ++j) {
                    float v0 = vals[2*j], v1 = vals[2*j+1];
                    __nv_bfloat16 h0 = __float2bfloat16_rn(v0);
                    __nv_bfloat16 h1 = __float2bfloat16_rn(v1);
                    __nv_bfloat16 l0 = __float2bfloat16_rn(v0 - __bfloat162float(h0));
                    __nv_bfloat16 l1 = __float2bfloat16_rn(v1 - __bfloat162float(h1));
                    uint32_t phi = (uint32_t)__bfloat16_as_ushort(h0) |
                                   ((uint32_t)__bfloat16_as_ushort(h1) << 16);
                    uint32_t plo = (uint32_t)__bfloat16_as_ushort(l0) |
                                   ((uint32_t)__bfloat16_as_ushort(l1) << 16);
                    uint32_t off = swaddr(bw, kb + 2*j);
                    *reinterpret_cast<uint32_t*>(smc + BHI_OFF + off) = phi;
                    *reinterpret_cast<uint32_t*>(smc + BLO_OFF + off) = plo;
                }
            }
            __syncthreads();

#pragma unroll 1
            for (int pass = 0; pass < 2; ++pass) {
                uint32_t Bbase = smem_base + (pass ? BLO_OFF : BHI_OFF);
#pragma unroll 4
                for (int kt = 0; kt < 24; ++kt) {
                    uint32_t ca = (uint32_t)(((2*kt + csa) ^ sw) << 4);
                    uint32_t cb = (uint32_t)(((2*kt + csb) ^ sw) << 4);
                    uint32_t a[4], b0[4], b1[4];
                    ldsm_x4(a,  a_row + ca);
                    ldsm_x4(b0, Bbase + b_row0 + cb);
                    ldsm_x4(b1, Bbase + b_row1 + cb);
                    mma_bf16(acc[0], a, b0);
                    mma_bf16(acc[1], a, b0 + 2);
                    mma_bf16(acc[2], a, b1);
                    mma_bf16(acc[3], a, b1 + 2);
                }
            }

            {
                int er = lane >> 2, ec = (lane & 3)*2;
#pragma unroll
                for (int nt = 0; nt < 4; ++nt) {
                    int col = n0 + nt*8 + ec;
                    *reinterpret_cast<float2*>(&zbuf[(m0 + er)*66 + col]) =
                        make_float2(acc[nt][0], acc[nt][1]);
                    *reinterpret_cast<float2*>(&zbuf[(m0 + er + 8)*66 + col]) =
                        make_float2(acc[nt][2], acc[nt][3]);
                }
            }
        }
        __syncthreads();

        // gates: z_ss[ol][w] = D[2ol][w] + D[2ol+1][w]
        float2 hres;
#pragma unroll
        for (int j = 0; j < 2; ++j) {
            int w = wg + j;
            float zs[4];
#pragma unroll
            for (int g = 0; g < 4; ++g) {
                if (r > 0) {
                    int rowA = (32*g + 2*cl);
                    zs[g] = zbuf[rowA*66 + w] + zbuf[(rowA + 1)*66 + w];
                } else zs[g] = 0.f;
            }
            float zi = zs[0] + sbv[0] + (j ? zv[0].y : zv[0].x);
            float zf = zs[1] + sbv[1] + (j ? zv[1].y : zv[1].x);
            float zo = zs[2] + sbv[2] + (j ? zv[2].y : zv[2].x);
            float zg = zs[3] + sbv[3] + (j ? zv[3].y : zv[3].x);
            float ig = 1.f / (1.f + __expf(-zi));
            float fg = 1.f / (1.f + __expf(-zf));
            float og = 1.f / (1.f + __expf(-zo));
            float gg = tanhf(zg);
            float cn = fg*cst[j] + ig*gg;
            cst[j] = cn;
            (&hres.x)[j] = og * tanhf(cn);
        }
        *reinterpret_cast<float2*>(&out[(((size_t)b*HID + chg)*Hh + r)*Ww + wg]) = hres;

        if (r < Hh - 1) {
            __stcg(reinterpret_cast<float2*>(
                &g_hbuf[r & 1][(b*HID + chg)*Ww + wg]), hres);
            __syncthreads();
            if (tid == 0) red_rel_gpu(cnt, 1u);
        }
    }

    // self-reset counters (graph replays reuse them); all CTAs have finished
    // their final poll of cnt before arriving on cnt2.
    __syncthreads();
    if (tid == 0) {
        red_rel_gpu(cnt2, 1u);
        if (hb == 0) {
            while (ld_acq_gpu(cnt2) < 8u) __nanosleep(32);
            st_rel_gpu(cnt,  0u);
            st_rel_gpu(cnt2, 0u);
        }
    }
}

// ---------------------------------------------------------------------------
extern "C" void kernel_launch(void* const* d_in, const int* in_sizes, int n_in,
                              void* d_out, int out_size) {
    const float* x   = (const float*)d_in[0];
    const float* Wis = (const float*)d_in[1];
    const float* bis = (const float*)d_in[2];
    const float* Wss = (const float*)d_in[3];
    const float* bss = (const float*)d_in[4];
    float* out = (float*)d_out;

    cudaFuncSetAttribute(kA_zis,  cudaFuncAttributeMaxDynamicSharedMemorySize, SMEM_KA);
    cudaFuncSetAttribute(kP_rows, cudaFuncAttributeMaxDynamicSharedMemorySize, SMEM_P);

    dim3 gA(Bb*Hh, OC/128);
    kA_zis<<<gA, 512, SMEM_KA>>>(x, Wis, bis);

    kP_rows<<<NCTA, 512, SMEM_P>>>(Wss, bss, out);
}

// round 14
// speedup vs baseline: 1.8410x; 1.2515x over previous
#include <cuda_runtime.h>
#include <cuda_bf16.h>
#include <cuda_fp16.h>
#include <stdint.h>
#include <math.h>

#define Bb   16
#define Cc   128
#define Hh   64
#define Ww   64
#define HID  128
#define OC   512
#define NCTA 128   // 16 b x 8 hid-blocks

typedef unsigned long long u64;

// Scratch (device globals: allocation-free per harness rules)
__device__ float    g_zis[(size_t)Bb*OC*Hh*Ww];   // [b, o, h, w]
__device__ float    g_hbuf[2][Bb*HID*Ww];         // double-buffered hidden state
__device__ unsigned g_cnt[32*32];                 // per-batch barrier counters
__device__ __half   g_wA[4][65536];               // preswizzled fp16 W_is images

__device__ __forceinline__ unsigned ld_acq_gpu(const unsigned* p) {
    unsigned v;
    asm volatile("ld.global.acquire.gpu.u32 %0, [%1];" : "=r"(v) : "l"(p) : "memory");
    return v;
}
__device__ __forceinline__ void red_rel_gpu(unsigned* p, unsigned v) {
    asm volatile("red.release.gpu.global.add.u32 [%0], %1;" :: "l"(p), "r"(v) : "memory");
}
__device__ __forceinline__ void st_rel_gpu(unsigned* p, unsigned v) {
    asm volatile("st.global.release.gpu.u32 [%0], %1;" :: "l"(p), "r"(v) : "memory");
}
__device__ __forceinline__ uint32_t smem_u32(const void* p) {
    uint32_t a;
    asm("{ .reg .u64 t; cvta.to.shared.u64 t, %1; cvt.u32.u64 %0, t; }" : "=r"(a) : "l"(p));
    return a;
}

// ---- legacy tensor-core helpers (sm_80+ PTX) -------------------------------
__device__ __forceinline__ void ldsm_x4(uint32_t* r, uint32_t addr) {
    asm volatile("ldmatrix.sync.aligned.m8n8.x4.shared.b16 {%0,%1,%2,%3}, [%4];"
                 : "=r"(r[0]), "=r"(r[1]), "=r"(r[2]), "=r"(r[3]) : "r"(addr));
}
__device__ __forceinline__ void mma_bf16(float* d, const uint32_t* a, const uint32_t* b) {
    asm volatile("mma.sync.aligned.m16n8k16.row.col.f32.bf16.bf16.f32 "
                 "{%0,%1,%2,%3}, {%4,%5,%6,%7}, {%8,%9}, {%0,%1,%2,%3};"
                 : "+f"(d[0]), "+f"(d[1]), "+f"(d[2]), "+f"(d[3])
                 : "r"(a[0]), "r"(a[1]), "r"(a[2]), "r"(a[3]), "r"(b[0]), "r"(b[1]));
}
__device__ __forceinline__ void mma_fp16(float* d, const uint32_t* a, const uint32_t* b) {
    asm volatile("mma.sync.aligned.m16n8k16.row.col.f32.f16.f16.f32 "
                 "{%0,%1,%2,%3}, {%4,%5,%6,%7}, {%8,%9}, {%0,%1,%2,%3};"
                 : "+f"(d[0]), "+f"(d[1]), "+f"(d[2]), "+f"(d[3])
                 : "r"(a[0]), "r"(a[1]), "r"(a[2]), "r"(a[3]), "r"(b[0]), "r"(b[1]));
}

// swizzles: 16B chunks XOR'ed by (row & 7); row strides 1024/512/256 bytes
__device__ __forceinline__ uint32_t swA(int row, int k) {
    return (uint32_t)(row*1024 + ((((k >> 3) ^ (row & 7)) << 4) | ((k & 7) << 1)));
}
__device__ __forceinline__ uint32_t swBx(int row, int k) {
    return (uint32_t)(row*512 + ((((k >> 3) ^ (row & 7)) << 4) | ((k & 7) << 1)));
}
__device__ __forceinline__ uint32_t sw256(int row, int k) {
    return (uint32_t)(row*256 + ((((k >> 3) ^ (row & 7)) << 4) | ((k & 7) << 1)));
}

// ---------------------------------------------------------------------------
// kW_prep: one-time conversion of W_is into preswizzled fp16 (hi|lo K-concat)
// g_wA[blk] is the exact byte image kA wants in smem. grid 32 x 256.
__global__ void kW_prep(const float* __restrict__ Wis) {
    int id = blockIdx.x * 256 + threadIdx.x;
    for (int it = 0; it < 16; ++it) {
        int idx = id + it*8192;               // 0 .. 131071
        int blk = idx >> 15;
        int r   = idx & 32767;
        int ol  = r >> 8;
        int k   = r & 255;
        int c = k >> 1, t = k & 1;
        float v = Wis[(size_t)(blk*128 + ol)*384 + c*3 + t];
        __half vh = __float2half_rn(v);
        __half vl = __float2half_rn(v - __half2float(vh));
        g_wA[blk][swA(ol, k) >> 1]       = vh;
        g_wA[blk][swA(ol, k + 256) >> 1] = vl;
    }
}

// ---------------------------------------------------------------------------
// Phase 1: masked input-to-state conv on tensor cores (fp16 two-term split).
#define KA_A_OFF  0          // fp16 A [128][512] swizzled        131072
#define KA_BH_OFF 131072     // fp16 Xhi [64][256] swizzled        32768
#define KA_BL_OFF 163840     // fp16 Xlo                           32768
#define KA_Z_OFF  196608     // fp32 zbuf [128][68] / xs [128][64] 34816
#define SMEM_KA   231424

__global__ void __launch_bounds__(512, 1)
kA_zis(const float* __restrict__ x,
       const float* __restrict__ Wis,
       const float* __restrict__ bis) {
    extern __shared__ char smc[];
    float* xs = reinterpret_cast<float*>(smc + KA_Z_OFF);   // [128][64]
    float* zb = reinterpret_cast<float*>(smc + KA_Z_OFF);   // [128][68] after MMA
    uint32_t sb = smem_u32(smc);

    int b  = blockIdx.x >> 6;
    int h  = blockIdx.x & 63;
    int o0 = blockIdx.y * 128;
    int tid = threadIdx.x, wid = tid >> 5, lane = tid & 31;

    // stage x row [128 c][64 w] (coalesced)
    for (int idx = tid; idx < 8192; idx += 512)
        xs[idx] = x[(((size_t)b*Cc + (idx >> 6))*Hh + h)*Ww + (idx & 63)];

    // stage preswizzled A image (straight float4 copy, L2-resident)
    {
        const float4* src = reinterpret_cast<const float4*>(g_wA[blockIdx.y]);
        float4* dst = reinterpret_cast<float4*>(smc + KA_A_OFF);
#pragma unroll
        for (int it = 0; it < 16; ++it)
            dst[tid + it*512] = __ldg(&src[tid + it*512]);
    }
    __syncthreads();

    // build B: B[w][2c] = x[c][w-1], B[w][2c+1] = x[c][w], split fp16 hi/lo
    {
        int bw = tid & 63, seg = tid >> 6;
#pragma unroll 4
        for (int i = 0; i < 16; ++i) {
            int c = seg*16 + i;
            float x0 = xs[c*64 + bw];
            float xm = bw ? xs[c*64 + bw - 1] : 0.f;
            __half h0 = __float2half_rn(xm), h1 = __float2half_rn(x0);
            __half l0 = __float2half_rn(xm - __half2float(h0));
            __half l1 = __float2half_rn(x0 - __half2float(h1));
            uint32_t phi = (uint32_t)__half_as_ushort(h0) | ((uint32_t)__half_as_ushort(h1) << 16);
            uint32_t plo = (uint32_t)__half_as_ushort(l0) | ((uint32_t)__half_as_ushort(l1) << 16);
            uint32_t off = swBx(bw, 2*c);
            *reinterpret_cast<uint32_t*>(smc + KA_BH_OFF + off) = phi;
            *reinterpret_cast<uint32_t*>(smc + KA_BL_OFF + off) = plo;
        }
    }
    __syncthreads();

    // MMA: warps (mt 0..7, nh 0..1)
    int mt = wid & 7, nh = wid >> 3;
    int m0 = mt*16, n0 = nh*32;
    int sw8 = lane & 7;
    int csa = lane >> 4;
    int bm  = lane >> 3, csb = bm & 1;
    int rbo = (bm >> 1)*8 + (lane & 7);
    uint32_t a_row = sb + KA_A_OFF + (uint32_t)(m0 + (lane & 15))*1024;
    uint32_t b_r0  = (uint32_t)(n0 + rbo)*512;
    uint32_t b_r1  = (uint32_t)(n0 + 16 + rbo)*512;

    float acc[4][4];
#pragma unroll
    for (int nt = 0; nt < 4; ++nt)
#pragma unroll
        for (int i = 0; i < 4; ++i) acc[nt][i] = 0.f;

#pragma unroll 4
    for (int kt = 0; kt < 48; ++kt) {
        int ktA = (kt < 32) ? kt : (kt - 32);
        int ktB = (kt < 32) ? (kt & 15) : (kt - 32);
        uint32_t Bbase = sb + ((kt < 32) ? KA_BH_OFF : KA_BL_OFF);
        uint32_t ca = (uint32_t)(((2*ktA + csa) ^ sw8) << 4);
        uint32_t cb = (uint32_t)(((2*ktB + csb) ^ sw8) << 4);
        uint32_t a[4], b0[4], b1[4];
        ldsm_x4(a,  a_row + ca);
        ldsm_x4(b0, Bbase + b_r0 + cb);
        ldsm_x4(b1, Bbase + b_r1 + cb);
        mma_fp16(acc[0], a, b0);
        mma_fp16(acc[1], a, b0 + 2);
        mma_fp16(acc[2], a, b1);
        mma_fp16(acc[3], a, b1 + 2);
    }

    {
        int er = lane >> 2, ec = (lane & 3)*2;
#pragma unroll
        for (int nt = 0; nt < 4; ++nt) {
            int col = n0 + nt*8 + ec;
            *reinterpret_cast<float2*>(&zb[(m0 + er)*68 + col]) =
                make_float2(acc[nt][0], acc[nt][1]);
            *reinterpret_cast<float2*>(&zb[(m0 + er + 8)*68 + col]) =
                make_float2(acc[nt][2], acc[nt][3]);
        }
    }
    __syncthreads();

    {
        int ol = tid >> 2, ws = (tid & 3)*16;
        float bv = bis[o0 + ol];
        float* dst = &g_zis[(((size_t)b*OC + o0 + ol)*Hh + h)*Ww + ws];
#pragma unroll
        for (int j = 0; j < 16; j += 4) {
            float4 v = *reinterpret_cast<const float4*>(&zb[ol*68 + ws + j]);
            v.x += bv; v.y += bv; v.z += bv; v.w += bv;
            *reinterpret_cast<float4*>(dst + j) = v;
        }
    }
}

// ---------------------------------------------------------------------------
// Phase 2: persistent recurrence, Toeplitz-factored tensor GEMM.
// P_k = A_k (128 rows: 2ol=Whi, 2ol+1=Wlo; 128 c) x H^T (64 w x 128 c, hi+lo).
// z[ol][w] = sum_k (P_k[2ol][w+k-1] + P_k[2ol+1][w+k-1]); row pairs combined
// in-register (shfl.bfly 4), shifts applied at the gate read.
#define BH_OFF2 98304        // A_k at k*32768 (3 x [128][256B])
#define BL_OFF2 114688
#define ZS_OFF2 131072       // union{ hs fp32 [128][68] ; zsum 3x[64][66] f32 }
#define SMEM_P  181760

__global__ void __launch_bounds__(512, 1)
kP_rows(const float* __restrict__ Wss,
        const float* __restrict__ bss,
        float* __restrict__ out) {
    extern __shared__ char smc[];
    float* hs   = reinterpret_cast<float*>(smc + ZS_OFF2);   // [128][68]
    float* zsum = reinterpret_cast<float*>(smc + ZS_OFF2);   // 3 x [64][66]
    uint32_t smem_base = smem_u32(smc);

    int b   = blockIdx.x >> 3;
    int hb  = blockIdx.x & 7;
    int tid = threadIdx.x;
    int wid = tid >> 5;
    int lane = tid & 31;
    unsigned* cnt  = &g_cnt[b*32];
    unsigned* cnt2 = &g_cnt[(16 + b)*32];

    // Build A_k files once: row 2ol = Whi, row 2ol+1 = Wlo, col = c
    for (int idx = tid; idx < 64*384; idx += 512) {
        int ol  = idx / 384;
        int rem = idx - ol*384;
        int o   = (ol >> 4)*128 + hb*16 + (ol & 15);
        float v = Wss[(size_t)o*384 + rem];
        int c = rem / 3, kk = rem - c*3;
        __nv_bfloat16 vh = __float2bfloat16_rn(v);
        __nv_bfloat16 vl = __float2bfloat16_rn(v - __bfloat162float(vh));
        char* base = smc + kk*32768;
        *reinterpret_cast<__nv_bfloat16*>(base + sw256(2*ol,     c)) = vh;
        *reinterpret_cast<__nv_bfloat16*>(base + sw256(2*ol + 1, c)) = vl;
    }

    // MMA warp mapping (proven lane math; row stride now 256B)
    int mt = wid & 7, nh = wid >> 3;
    int m0 = mt*16, n0 = nh*32;
    int sw   = lane & 7;
    int csa  = lane >> 4;
    int bm   = lane >> 3;
    int csb  = bm & 1;
    int rbo  = (bm >> 1)*8 + (lane & 7);
    uint32_t aK0 = smem_base + 0*32768 + (uint32_t)(m0 + (lane & 15))*256;
    uint32_t aK1 = smem_base + 1*32768 + (uint32_t)(m0 + (lane & 15))*256;
    uint32_t aK2 = smem_base + 2*32768 + (uint32_t)(m0 + (lane & 15))*256;
    uint32_t brow0 = (uint32_t)(n0 + rbo)*256;
    uint32_t brow1 = (uint32_t)(n0 + 16 + rbo)*256;

    // gate-phase mapping: cl channel-local, 2 consecutive w per thread
    int cl  = tid >> 5;
    int wg  = (tid & 31) * 2;
    int chg = hb*16 + cl;
    float sbv[4];
#pragma unroll
    for (int g = 0; g < 4; ++g) sbv[g] = bss[g*128 + chg];
    float cst[2] = {0.f, 0.f};

    // B-build mapping: row bw = tid&63 (w), seg = tid>>6 (16 c's each)
    int bw  = tid & 63;
    int seg = tid >> 6;

    // epilogue mapping
    int er = lane >> 2, ec = (lane & 3)*2;
    int olA = mt*8 + (er >> 1);
    bool estore = ((lane & 4) == 0);

    const float* zisb = g_zis + (size_t)b*OC*Hh*Ww;
    __syncthreads();

    for (int r = 0; r < Hh; ++r) {
        // prefetch z_is for gates (overlaps barrier poll)
        float2 zv[4];
#pragma unroll
        for (int g = 0; g < 4; ++g)
            zv[g] = *reinterpret_cast<const float2*>(
                &zisb[(((size_t)(g*128 + chg))*Hh + r)*Ww + wg]);

        if (r > 0) {
            if (tid == 0) {
                unsigned target = 8u * (unsigned)r;
                while (ld_acq_gpu(cnt) < target) __nanosleep(32);
            }
            __syncthreads();
            // reload h into hs [128][68] (cols 0..63)
            {
                const float4* hsrc = reinterpret_cast<const float4*>(
                    g_hbuf[(r-1) & 1] + b*HID*Ww);
#pragma unroll
                for (int it = 0; it < 4; ++it) {
                    int j = tid + it*512;
                    int c = j >> 4, w4 = (j & 15) * 4;
                    float4 v = __ldcg(&hsrc[j]);
                    *reinterpret_cast<float4*>(&hs[c*68 + w4]) = v;
                }
            }
            __syncthreads();

            // build H^T hi/lo: B[w][c] = h[c][w], 8 c-pairs per thread
#pragma unroll 4
            for (int i = 0; i < 8; ++i) {
                int c = seg*16 + 2*i;
                float v0 = hs[c*68 + bw];
                float v1 = hs[(c+1)*68 + bw];
                __nv_bfloat16 h0 = __float2bfloat16_rn(v0);
                __nv_bfloat16 h1 = __float2bfloat16_rn(v1);
                __nv_bfloat16 l0 = __float2bfloat16_rn(v0 - __bfloat162float(h0));
                __nv_bfloat16 l1 = __float2bfloat16_rn(v1 - __bfloat162float(h1));
                uint32_t phi = (uint32_t)__bfloat16_as_ushort(h0) |
                               ((uint32_t)__bfloat16_as_ushort(h1) << 16);
                uint32_t plo = (uint32_t)__bfloat16_as_ushort(l0) |
                               ((uint32_t)__bfloat16_as_ushort(l1) << 16);
                uint32_t off = sw256(bw, c);
                *reinterpret_cast<uint32_t*>(smc + BH_OFF2 + off) = phi;
                *reinterpret_cast<uint32_t*>(smc + BL_OFF2 + off) = plo;
            }
            __syncthreads();

            // 3-tap factored GEMM: P_k accumulators, shared B fragments
            float acc[3][4][4];
#pragma unroll
            for (int k = 0; k < 3; ++k)
#pragma unroll
                for (int nt = 0; nt < 4; ++nt)
#pragma unroll
                    for (int i = 0; i < 4; ++i) acc[k][nt][i] = 0.f;

#pragma unroll 2
            for (int kt = 0; kt < 8; ++kt) {
                uint32_t ca = (uint32_t)(((2*kt + csa) ^ sw) << 4);
                uint32_t cb = (uint32_t)(((2*kt + csb) ^ sw) << 4);
                uint32_t a0[4], a1[4], a2[4], b0[4], b1[4];
                ldsm_x4(a0, aK0 + ca);
                ldsm_x4(a1, aK1 + ca);
                ldsm_x4(a2, aK2 + ca);
                // hi pass
                ldsm_x4(b0, smem_base + BH_OFF2 + brow0 + cb);
                ldsm_x4(b1, smem_base + BH_OFF2 + brow1 + cb);
                mma_bf16(acc[0][0], a0, b0); mma_bf16(acc[0][1], a0, b0+2);
                mma_bf16(acc[0][2], a0, b1); mma_bf16(acc[0][3], a0, b1+2);
                mma_bf16(acc[1][0], a1, b0); mma_bf16(acc[1][1], a1, b0+2);
                mma_bf16(acc[1][2], a1, b1); mma_bf16(acc[1][3], a1, b1+2);
                mma_bf16(acc[2][0], a2, b0); mma_bf16(acc[2][1], a2, b0+2);
                mma_bf16(acc[2][2], a2, b1); mma_bf16(acc[2][3], a2, b1+2);
                // lo pass (same A, same acc)
                ldsm_x4(b0, smem_base + BL_OFF2 + brow0 + cb);
                ldsm_x4(b1, smem_base + BL_OFF2 + brow1 + cb);
                mma_bf16(acc[0][0], a0, b0); mma_bf16(acc[0][1], a0, b0+2);
                mma_bf16(acc[0][2], a0, b1); mma_bf16(acc[0][3], a0, b1+2);
                mma_bf16(acc[1][0], a1, b0); mma_bf16(acc[1][1], a1, b0+2);
                mma_bf16(acc[1][2], a1, b1); mma_bf16(acc[1][3], a1, b1+2);
                mma_bf16(acc[2][0], a2, b0); mma_bf16(acc[2][1], a2, b0+2);
                mma_bf16(acc[2][2], a2, b1); mma_bf16(acc[2][3], a2, b1+2);
            }
            __syncthreads();   // hs reads fully done before zsum overwrite

            // epilogue: combine hi/lo row pairs (shfl.bfly 4), store zsum[k]
#pragma unroll
            for (int k = 0; k < 3; ++k) {
#pragma unroll
                for (int nt = 0; nt < 4; ++nt) {
                    int col = n0 + nt*8 + ec;
                    float s0 = acc[k][nt][0] + __shfl_xor_sync(0xffffffffu, acc[k][nt][0], 4);
                    float s1 = acc[k][nt][1] + __shfl_xor_sync(0xffffffffu, acc[k][nt][1], 4);
                    float s2 = acc[k][nt][2] + __shfl_xor_sync(0xffffffffu, acc[k][nt][2], 4);
                    float s3 = acc[k][nt][3] + __shfl_xor_sync(0xffffffffu, acc[k][nt][3], 4);
                    if (estore) {
                        *reinterpret_cast<float2*>(&zsum[k*4224 + olA*66 + col]) =
                            make_float2(s0, s1);
                        *reinterpret_cast<float2*>(&zsum[k*4224 + (olA + 4)*66 + col]) =
                            make_float2(s2, s3);
                    }
                }
            }
        }
        __syncthreads();

        // gates: z_ss[ol][w] = sum_k zsum[k][ol][w+k-1] (bounds-guarded)
        float2 hres;
#pragma unroll
        for (int j = 0; j < 2; ++j) {
            int w = wg + j;
            float zs[4];
#pragma unroll
            for (int g = 0; g < 4; ++g) {
                float s = 0.f;
                if (r > 0) {
                    int olg = g*16 + cl;
                    if (w >= 1)  s += zsum[0*4224 + olg*66 + (w - 1)];
                    s += zsum[1*4224 + olg*66 + w];
                    if (w <= 62) s += zsum[2*4224 + olg*66 + (w + 1)];
                }
                zs[g] = s;
            }
            float zi = zs[0] + sbv[0] + (j ? zv[0].y : zv[0].x);
            float zf = zs[1] + sbv[1] + (j ? zv[1].y : zv[1].x);
            float zo = zs[2] + sbv[2] + (j ? zv[2].y : zv[2].x);
            float zg = zs[3] + sbv[3] + (j ? zv[3].y : zv[3].x);
            float ig = 1.f / (1.f + __expf(-zi));
            float fg = 1.f / (1.f + __expf(-zf));
            float og = 1.f / (1.f + __expf(-zo));
            float gg = tanhf(zg);
            float cn = fg*cst[j] + ig*gg;
            cst[j] = cn;
            (&hres.x)[j] = og * tanhf(cn);
        }
        *reinterpret_cast<float2*>(&out[(((size_t)b*HID + chg)*Hh + r)*Ww + wg]) = hres;

        if (r < Hh - 1) {
            __stcg(reinterpret_cast<float2*>(
                &g_hbuf[r & 1][(b*HID + chg)*Ww + wg]), hres);
            __syncthreads();
            if (tid == 0) red_rel_gpu(cnt, 1u);
        }
    }

    // self-reset counters for graph replays
    __syncthreads();
    if (tid == 0) {
        red_rel_gpu(cnt2, 1u);
        if (hb == 0) {
            while (ld_acq_gpu(cnt2) < 8u) __nanosleep(32);
            st_rel_gpu(cnt,  0u);
            st_rel_gpu(cnt2, 0u);
        }
    }
}

// ---------------------------------------------------------------------------
extern "C" void kernel_launch(void* const* d_in, const int* in_sizes, int n_in,
                              void* d_out, int out_size) {
    const float* x   = (const float*)d_in[0];
    const float* Wis = (const float*)d_in[1];
    const float* bis = (const float*)d_in[2];
    const float* Wss = (const float*)d_in[3];
    const float* bss = (const float*)d_in[4];
    float* out = (float*)d_out;

    cudaFuncSetAttribute(kA_zis,  cudaFuncAttributeMaxDynamicSharedMemorySize, SMEM_KA);
    cudaFuncSetAttribute(kP_rows, cudaFuncAttributeMaxDynamicSharedMemorySize, SMEM_P);

    kW_prep<<<32, 256>>>(Wis);

    dim3 gA(Bb*Hh, OC/128);
    kA_zis<<<gA, 512, SMEM_KA>>>(x, Wis, bis);

    kP_rows<<<NCTA, 512, SMEM_P>>>(Wss, bss, out);
}

// round 15
// speedup vs baseline: 2.1405x; 1.1627x over previous
#include <cuda_runtime.h>
#include <cuda_bf16.h>
#include <cuda_fp16.h>
#include <stdint.h>
#include <math.h>

#define Bb   16
#define Cc   128
#define Hh   64
#define Ww   64
#define HID  128
#define OC   512
#define NCTA 128   // 16 b x 8 hid-blocks

typedef unsigned long long u64;

// Scratch (device globals). NOTE transposed layouts (private to this kernel):
//   g_zis : [b][h][w][o]   (o contiguous, 512)
//   g_hbuf: [buf][b][w][c] (c contiguous, 128)
__device__ float    g_zis[(size_t)Bb*Hh*Ww*OC];
__device__ float    g_hbuf[2][Bb*Ww*HID];
__device__ unsigned g_cnt[32*32];
__device__ __half   g_wA[4][65536];               // preswizzled fp16 W_is images

__device__ __forceinline__ unsigned ld_acq_gpu(const unsigned* p) {
    unsigned v;
    asm volatile("ld.global.acquire.gpu.u32 %0, [%1];" : "=r"(v) : "l"(p) : "memory");
    return v;
}
__device__ __forceinline__ void red_rel_gpu(unsigned* p, unsigned v) {
    asm volatile("red.release.gpu.global.add.u32 [%0], %1;" :: "l"(p), "r"(v) : "memory");
}
__device__ __forceinline__ void st_rel_gpu(unsigned* p, unsigned v) {
    asm volatile("st.global.release.gpu.u32 [%0], %1;" :: "l"(p), "r"(v) : "memory");
}
__device__ __forceinline__ uint32_t smem_u32(const void* p) {
    uint32_t a;
    asm("{ .reg .u64 t; cvta.to.shared.u64 t, %1; cvt.u32.u64 %0, t; }" : "=r"(a) : "l"(p));
    return a;
}

// ---- legacy tensor-core helpers (sm_80+ PTX) -------------------------------
__device__ __forceinline__ void ldsm_x4(uint32_t* r, uint32_t addr) {
    asm volatile("ldmatrix.sync.aligned.m8n8.x4.shared.b16 {%0,%1,%2,%3}, [%4];"
                 : "=r"(r[0]), "=r"(r[1]), "=r"(r[2]), "=r"(r[3]) : "r"(addr));
}
__device__ __forceinline__ void mma_bf16(float* d, const uint32_t* a, const uint32_t* b) {
    asm volatile("mma.sync.aligned.m16n8k16.row.col.f32.bf16.bf16.f32 "
                 "{%0,%1,%2,%3}, {%4,%5,%6,%7}, {%8,%9}, {%0,%1,%2,%3};"
                 : "+f"(d[0]), "+f"(d[1]), "+f"(d[2]), "+f"(d[3])
                 : "r"(a[0]), "r"(a[1]), "r"(a[2]), "r"(a[3]), "r"(b[0]), "r"(b[1]));
}
__device__ __forceinline__ void mma_fp16(float* d, const uint32_t* a, const uint32_t* b) {
    asm volatile("mma.sync.aligned.m16n8k16.row.col.f32.f16.f16.f32 "
                 "{%0,%1,%2,%3}, {%4,%5,%6,%7}, {%8,%9}, {%0,%1,%2,%3};"
                 : "+f"(d[0]), "+f"(d[1]), "+f"(d[2]), "+f"(d[3])
                 : "r"(a[0]), "r"(a[1]), "r"(a[2]), "r"(a[3]), "r"(b[0]), "r"(b[1]));
}

// swizzles: 16B chunks XOR'ed by (row & 7); row strides 1024/512/256 bytes
__device__ __forceinline__ uint32_t swA(int row, int k) {
    return (uint32_t)(row*1024 + ((((k >> 3) ^ (row & 7)) << 4) | ((k & 7) << 1)));
}
__device__ __forceinline__ uint32_t swBx(int row, int k) {
    return (uint32_t)(row*512 + ((((k >> 3) ^ (row & 7)) << 4) | ((k & 7) << 1)));
}
__device__ __forceinline__ uint32_t sw256(int row, int k) {
    return (uint32_t)(row*256 + ((((k >> 3) ^ (row & 7)) << 4) | ((k & 7) << 1)));
}

// ---------------------------------------------------------------------------
// kW_prep: one-time conversion of W_is into preswizzled fp16 (hi|lo K-concat)
__global__ void kW_prep(const float* __restrict__ Wis) {
    int id = blockIdx.x * 256 + threadIdx.x;
    for (int it = 0; it < 16; ++it) {
        int idx = id + it*8192;
        int blk = idx >> 15;
        int r   = idx & 32767;
        int ol  = r >> 8;
        int k   = r & 255;
        int c = k >> 1, t = k & 1;
        float v = Wis[(size_t)(blk*128 + ol)*384 + c*3 + t];
        __half vh = __float2half_rn(v);
        __half vl = __float2half_rn(v - __half2float(vh));
        g_wA[blk][swA(ol, k) >> 1]       = vh;
        g_wA[blk][swA(ol, k + 256) >> 1] = vl;
    }
}

// ---------------------------------------------------------------------------
// Phase 1: masked input-to-state conv, 4 h-rows per CTA.
#define KA_A_OFF  0          // fp16 A [128][512] swizzled        131072
#define KA_BH_OFF 131072     // fp16 Xhi [64][256] swizzled        32768
#define KA_BL_OFF 163840     // fp16 Xlo                           32768
#define KA_Z_OFF  196608     // union{ xs [128][64] f32 ; zbt [64][132] f32 }
#define SMEM_KA   230400

__global__ void __launch_bounds__(512, 1)
kA_zis(const float* __restrict__ x,
       const float* __restrict__ Wis,
       const float* __restrict__ bis) {
    extern __shared__ char smc[];
    float* xs  = reinterpret_cast<float*>(smc + KA_Z_OFF);   // [128][64]
    float* zbt = reinterpret_cast<float*>(smc + KA_Z_OFF);   // [64][132] after GEMM
    uint32_t sb = smem_u32(smc);

    int b  = blockIdx.x >> 4;
    int hq = blockIdx.x & 15;
    int ob = blockIdx.y;
    int tid = threadIdx.x, wid = tid >> 5, lane = tid & 31;

    // stage preswizzled A image once (float4 copy, L2-resident)
    {
        const float4* src = reinterpret_cast<const float4*>(g_wA[ob]);
        float4* dst = reinterpret_cast<float4*>(smc + KA_A_OFF);
#pragma unroll
        for (int it = 0; it < 16; ++it)
            dst[tid + it*512] = __ldg(&src[tid + it*512]);
    }

    // per-thread z-write mapping + bias preload
    int zw = tid >> 3, zq = tid & 7;
    float bv[16];
#pragma unroll
    for (int j = 0; j < 16; ++j) bv[j] = bis[ob*128 + zq*16 + j];

    // MMA mapping
    int mt = wid & 7, nh = wid >> 3;
    int m0 = mt*16, n0 = nh*32;
    int sw8 = lane & 7;
    int csa = lane >> 4;
    int bm  = lane >> 3, csb = bm & 1;
    int rbo = (bm >> 1)*8 + (lane & 7);
    uint32_t a_row = sb + KA_A_OFF + (uint32_t)(m0 + (lane & 15))*1024;
    uint32_t b_r0  = (uint32_t)(n0 + rbo)*512;
    uint32_t b_r1  = (uint32_t)(n0 + 16 + rbo)*512;
    int er = lane >> 2, ec = (lane & 3)*2;

    for (int rr = 0; rr < 4; ++rr) {
        int h = hq*4 + rr;
        if (rr > 0) __syncthreads();       // zbt reads done before xs overwrite

        for (int idx = tid; idx < 8192; idx += 512)
            xs[idx] = x[(((size_t)b*Cc + (idx >> 6))*Hh + h)*Ww + (idx & 63)];
        __syncthreads();

        // build B: B[w][2c]=x[c][w-1], B[w][2c+1]=x[c][w], split fp16 hi/lo
        {
            int bw = tid & 63, seg = tid >> 6;
#pragma unroll 4
            for (int i = 0; i < 16; ++i) {
                int c = seg*16 + i;
                float x0 = xs[c*64 + bw];
                float xm = bw ? xs[c*64 + bw - 1] : 0.f;
                __half h0 = __float2half_rn(xm), h1 = __float2half_rn(x0);
                __half l0 = __float2half_rn(xm - __half2float(h0));
                __half l1 = __float2half_rn(x0 - __half2float(h1));
                uint32_t phi = (uint32_t)__half_as_ushort(h0) | ((uint32_t)__half_as_ushort(h1) << 16);
                uint32_t plo = (uint32_t)__half_as_ushort(l0) | ((uint32_t)__half_as_ushort(l1) << 16);
                uint32_t off = swBx(bw, 2*c);
                *reinterpret_cast<uint32_t*>(smc + KA_BH_OFF + off) = phi;
                *reinterpret_cast<uint32_t*>(smc + KA_BL_OFF + off) = plo;
            }
        }
        __syncthreads();

        float acc[4][4];
#pragma unroll
        for (int nt = 0; nt < 4; ++nt)
#pragma unroll
            for (int i = 0; i < 4; ++i) acc[nt][i] = 0.f;

#pragma unroll 4
        for (int kt = 0; kt < 48; ++kt) {
            int ktA = (kt < 32) ? kt : (kt - 32);
            int ktB = (kt < 32) ? (kt & 15) : (kt - 32);
            uint32_t Bbase = sb + ((kt < 32) ? KA_BH_OFF : KA_BL_OFF);
            uint32_t ca = (uint32_t)(((2*ktA + csa) ^ sw8) << 4);
            uint32_t cb = (uint32_t)(((2*ktB + csb) ^ sw8) << 4);
            uint32_t a[4], b0[4], b1[4];
            ldsm_x4(a,  a_row + ca);
            ldsm_x4(b0, Bbase + b_r0 + cb);
            ldsm_x4(b1, Bbase + b_r1 + cb);
            mma_fp16(acc[0], a, b0);
            mma_fp16(acc[1], a, b0 + 2);
            mma_fp16(acc[2], a, b1);
            mma_fp16(acc[3], a, b1 + 2);
        }

        // epilogue: store TRANSPOSED zbt[w][o] (stride 132; bank-clean scalars)
#pragma unroll
        for (int nt = 0; nt < 4; ++nt) {
            int col = n0 + nt*8 + ec;
            zbt[col*132 + m0 + er]           = acc[nt][0];
            zbt[(col + 1)*132 + m0 + er]     = acc[nt][1];
            zbt[col*132 + m0 + er + 8]       = acc[nt][2];
            zbt[(col + 1)*132 + m0 + er + 8] = acc[nt][3];
        }
        __syncthreads();

        // write z_is[b][h][w][o] + bias (coalesced: 8 lanes cover 128 o floats)
        {
            float* dst = &g_zis[(((size_t)b*Hh + h)*Ww + zw)*OC + ob*128 + zq*16];
#pragma unroll
            for (int j = 0; j < 16; j += 4) {
                float4 v = *reinterpret_cast<const float4*>(&zbt[zw*132 + zq*16 + j]);
                v.x += bv[j]; v.y += bv[j+1]; v.z += bv[j+2]; v.w += bv[j+3];
                *reinterpret_cast<float4*>(dst + j) = v;
            }
        }
    }
}

// ---------------------------------------------------------------------------
// Phase 2: persistent recurrence, Toeplitz-factored tensor GEMM.
// h stored transposed ([b][w][c]) -> B-build reads gmem directly (no staging).
#define BH_OFF2 98304        // A_k at k*32768 (3 x [128][256B])
#define BL_OFF2 114688
#define ZS_OFF2 131072       // zsum 3 x [64][66] f32
#define SMEM_P  181760

__global__ void __launch_bounds__(512, 1)
kP_rows(const float* __restrict__ Wss,
        const float* __restrict__ bss,
        float* __restrict__ out) {
    extern __shared__ char smc[];
    float* zsum = reinterpret_cast<float*>(smc + ZS_OFF2);   // 3 x [64][66]
    uint32_t smem_base = smem_u32(smc);

    int b   = blockIdx.x >> 3;
    int hb  = blockIdx.x & 7;
    int tid = threadIdx.x;
    int wid = tid >> 5;
    int lane = tid & 31;
    unsigned* cnt  = &g_cnt[b*32];
    unsigned* cnt2 = &g_cnt[(16 + b)*32];

    // Build A_k files once: row 2ol = Whi, row 2ol+1 = Wlo, col = c
    for (int idx = tid; idx < 64*384; idx += 512) {
        int ol  = idx / 384;
        int rem = idx - ol*384;
        int o   = (ol >> 4)*128 + hb*16 + (ol & 15);
        float v = Wss[(size_t)o*384 + rem];
        int c = rem / 3, kk = rem - c*3;
        __nv_bfloat16 vh = __float2bfloat16_rn(v);
        __nv_bfloat16 vl = __float2bfloat16_rn(v - __bfloat162float(vh));
        char* base = smc + kk*32768;
        *reinterpret_cast<__nv_bfloat16*>(base + sw256(2*ol,     c)) = vh;
        *reinterpret_cast<__nv_bfloat16*>(base + sw256(2*ol + 1, c)) = vl;
    }

    // MMA warp mapping
    int mt = wid & 7, nh = wid >> 3;
    int m0 = mt*16, n0 = nh*32;
    int sw   = lane & 7;
    int csa  = lane >> 4;
    int bm   = lane >> 3;
    int csb  = bm & 1;
    int rbo  = (bm >> 1)*8 + (lane & 7);
    uint32_t aK0 = smem_base + 0*32768 + (uint32_t)(m0 + (lane & 15))*256;
    uint32_t aK1 = smem_base + 1*32768 + (uint32_t)(m0 + (lane & 15))*256;
    uint32_t aK2 = smem_base + 2*32768 + (uint32_t)(m0 + (lane & 15))*256;
    uint32_t brow0 = (uint32_t)(n0 + rbo)*256;
    uint32_t brow1 = (uint32_t)(n0 + 16 + rbo)*256;

    // gate-phase mapping: thread = (w = tid>>3, q = tid&7) -> channels 2q, 2q+1
    int gw = tid >> 3;
    int gq = tid & 7;
    int ch0 = hb*16 + 2*gq;                 // and ch0+1
    float sbv[4][2];
#pragma unroll
    for (int g = 0; g < 4; ++g) {
        sbv[g][0] = bss[g*128 + ch0];
        sbv[g][1] = bss[g*128 + ch0 + 1];
    }
    float cst[2] = {0.f, 0.f};

    // epilogue mapping
    int er = lane >> 2, ec = (lane & 3)*2;
    int olA = mt*8 + (er >> 1);
    bool estore = ((lane & 4) == 0);

    __syncthreads();

    for (int r = 0; r < Hh; ++r) {
        // prefetch z_is[b][r][w][o] (new layout: float2 per gate group, coalesced)
        float2 zv[4];
        {
            const float* zrow = &g_zis[(((size_t)b*Hh + r)*Ww + gw)*OC];
#pragma unroll
            for (int g = 0; g < 4; ++g)
                zv[g] = *reinterpret_cast<const float2*>(&zrow[g*128 + ch0]);
        }

        if (r > 0) {
            if (tid == 0) {
                unsigned target = 8u * (unsigned)r;
                while (ld_acq_gpu(cnt) < target) __nanosleep(32);
            }
            __syncthreads();

            // B-build straight from g_hbuf[b][w][c] (coalesced float4 reads)
            {
                const float4* hsrc = reinterpret_cast<const float4*>(
                    g_hbuf[(r-1) & 1] + (size_t)b*Ww*HID);
#pragma unroll
                for (int it = 0; it < 4; ++it) {
                    int j = tid + it*512;           // 0..2047
                    int w = j >> 5, c4 = j & 31;    // c = 4*c4
                    float4 v = __ldcg(&hsrc[j]);
                    int c = c4*4;
                    __nv_bfloat16 h0 = __float2bfloat16_rn(v.x);
                    __nv_bfloat16 h1 = __float2bfloat16_rn(v.y);
                    __nv_bfloat16 h2 = __float2bfloat16_rn(v.z);
                    __nv_bfloat16 h3 = __float2bfloat16_rn(v.w);
                    __nv_bfloat16 l0 = __float2bfloat16_rn(v.x - __bfloat162float(h0));
                    __nv_bfloat16 l1 = __float2bfloat16_rn(v.y - __bfloat162float(h1));
                    __nv_bfloat16 l2 = __float2bfloat16_rn(v.z - __bfloat162float(h2));
                    __nv_bfloat16 l3 = __float2bfloat16_rn(v.w - __bfloat162float(h3));
                    uint32_t hiA = (uint32_t)__bfloat16_as_ushort(h0) |
                                   ((uint32_t)__bfloat16_as_ushort(h1) << 16);
                    uint32_t hiB = (uint32_t)__bfloat16_as_ushort(h2) |
                                   ((uint32_t)__bfloat16_as_ushort(h3) << 16);
                    uint32_t loA = (uint32_t)__bfloat16_as_ushort(l0) |
                                   ((uint32_t)__bfloat16_as_ushort(l1) << 16);
                    uint32_t loB = (uint32_t)__bfloat16_as_ushort(l2) |
                                   ((uint32_t)__bfloat16_as_ushort(l3) << 16);
                    uint32_t offA = sw256(w, c);
                    uint32_t offB = sw256(w, c + 2);
                    *reinterpret_cast<uint32_t*>(smc + BH_OFF2 + offA) = hiA;
                    *reinterpret_cast<uint32_t*>(smc + BH_OFF2 + offB) = hiB;
                    *reinterpret_cast<uint32_t*>(smc + BL_OFF2 + offA) = loA;
                    *reinterpret_cast<uint32_t*>(smc + BL_OFF2 + offB) = loB;
                }
            }
            __syncthreads();

            // 3-tap factored GEMM
            float acc[3][4][4];
#pragma unroll
            for (int k = 0; k < 3; ++k)
#pragma unroll
                for (int nt = 0; nt < 4; ++nt)
#pragma unroll
                    for (int i = 0; i < 4; ++i) acc[k][nt][i] = 0.f;

#pragma unroll 2
            for (int kt = 0; kt < 8; ++kt) {
                uint32_t ca = (uint32_t)(((2*kt + csa) ^ sw) << 4);
                uint32_t cb = (uint32_t)(((2*kt + csb) ^ sw) << 4);
                uint32_t a0[4], a1[4], a2[4], b0[4], b1[4];
                ldsm_x4(a0, aK0 + ca);
                ldsm_x4(a1, aK1 + ca);
                ldsm_x4(a2, aK2 + ca);
                ldsm_x4(b0, smem_base + BH_OFF2 + brow0 + cb);
                ldsm_x4(b1, smem_base + BH_OFF2 + brow1 + cb);
                mma_bf16(acc[0][0], a0, b0); mma_bf16(acc[0][1], a0, b0+2);
                mma_bf16(acc[0][2], a0, b1); mma_bf16(acc[0][3], a0, b1+2);
                mma_bf16(acc[1][0], a1, b0); mma_bf16(acc[1][1], a1, b0+2);
                mma_bf16(acc[1][2], a1, b1); mma_bf16(acc[1][3], a1, b1+2);
                mma_bf16(acc[2][0], a2, b0); mma_bf16(acc[2][1], a2, b0+2);
                mma_bf16(acc[2][2], a2, b1); mma_bf16(acc[2][3], a2, b1+2);
                ldsm_x4(b0, smem_base + BL_OFF2 + brow0 + cb);
                ldsm_x4(b1, smem_base + BL_OFF2 + brow1 + cb);
                mma_bf16(acc[0][0], a0, b0); mma_bf16(acc[0][1], a0, b0+2);
                mma_bf16(acc[0][2], a0, b1); mma_bf16(acc[0][3], a0, b1+2);
                mma_bf16(acc[1][0], a1, b0); mma_bf16(acc[1][1], a1, b0+2);
                mma_bf16(acc[1][2], a1, b1); mma_bf16(acc[1][3], a1, b1+2);
                mma_bf16(acc[2][0], a2, b0); mma_bf16(acc[2][1], a2, b0+2);
                mma_bf16(acc[2][2], a2, b1); mma_bf16(acc[2][3], a2, b1+2);
            }

            // epilogue: combine hi/lo row pairs (shfl.bfly 4), store zsum[k]
#pragma unroll
            for (int k = 0; k < 3; ++k) {
#pragma unroll
                for (int nt = 0; nt < 4; ++nt) {
                    int col = n0 + nt*8 + ec;
                    float s0 = acc[k][nt][0] + __shfl_xor_sync(0xffffffffu, acc[k][nt][0], 4);
                    float s1 = acc[k][nt][1] + __shfl_xor_sync(0xffffffffu, acc[k][nt][1], 4);
                    float s2 = acc[k][nt][2] + __shfl_xor_sync(0xffffffffu, acc[k][nt][2], 4);
                    float s3 = acc[k][nt][3] + __shfl_xor_sync(0xffffffffu, acc[k][nt][3], 4);
                    if (estore) {
                        *reinterpret_cast<float2*>(&zsum[k*4224 + olA*66 + col]) =
                            make_float2(s0, s1);
                        *reinterpret_cast<float2*>(&zsum[k*4224 + (olA + 4)*66 + col]) =
                            make_float2(s2, s3);
                    }
                }
            }
        }
        __syncthreads();

        // gates at (w = gw, channels ch0, ch0+1)
        float hres[2];
#pragma unroll
        for (int j = 0; j < 2; ++j) {
            int cl = 2*gq + j;
            float zs[4];
#pragma unroll
            for (int g = 0; g < 4; ++g) {
                float s = 0.f;
                if (r > 0) {
                    int olg = g*16 + cl;
                    if (gw >= 1)  s += zsum[0*4224 + olg*66 + (gw - 1)];
                    s += zsum[1*4224 + olg*66 + gw];
                    if (gw <= 62) s += zsum[2*4224 + olg*66 + (gw + 1)];
                }
                zs[g] = s;
            }
            float zi = zs[0] + sbv[0][j] + (j ? zv[0].y : zv[0].x);
            float zf = zs[1] + sbv[1][j] + (j ? zv[1].y : zv[1].x);
            float zo = zs[2] + sbv[2][j] + (j ? zv[2].y : zv[2].x);
            float zg = zs[3] + sbv[3][j] + (j ? zv[3].y : zv[3].x);
            float ig = 1.f / (1.f + __expf(-zi));
            float fg = 1.f / (1.f + __expf(-zf));
            float og = 1.f / (1.f + __expf(-zo));
            float gg = tanhf(zg);
            float cn = fg*cst[j] + ig*gg;
            cst[j] = cn;
            hres[j] = og * tanhf(cn);
        }
        out[(((size_t)b*HID + ch0)*Hh + r)*Ww + gw]     = hres[0];
        out[(((size_t)b*HID + ch0 + 1)*Hh + r)*Ww + gw] = hres[1];

        if (r < Hh - 1) {
            // publish h transposed: g_hbuf[buf][b][w][c] (float2, coalesced)
            __stcg(reinterpret_cast<float2*>(
                &g_hbuf[r & 1][((size_t)b*Ww + gw)*HID + ch0]),
                make_float2(hres[0], hres[1]));
            __syncthreads();
            if (tid == 0) red_rel_gpu(cnt, 1u);
        }
    }

    // self-reset counters for graph replays
    __syncthreads();
    if (tid == 0) {
        red_rel_gpu(cnt2, 1u);
        if (hb == 0) {
            while (ld_acq_gpu(cnt2) < 8u) __nanosleep(32);
            st_rel_gpu(cnt,  0u);
            st_rel_gpu(cnt2, 0u);
        }
    }
}

// ---------------------------------------------------------------------------
extern "C" void kernel_launch(void* const* d_in, const int* in_sizes, int n_in,
                              void* d_out, int out_size) {
    const float* x   = (const float*)d_in[0];
    const float* Wis = (const float*)d_in[1];
    const float* bis = (const float*)d_in[2];
    const float* Wss = (const float*)d_in[3];
    const float* bss = (const float*)d_in[4];
    float* out = (float*)d_out;

    cudaFuncSetAttribute(kA_zis,  cudaFuncAttributeMaxDynamicSharedMemorySize, SMEM_KA);
    cudaFuncSetAttribute(kP_rows, cudaFuncAttributeMaxDynamicSharedMemorySize, SMEM_P);

    kW_prep<<<32, 256>>>(Wis);

    dim3 gA(Bb*16, OC/128);   // 4 h-rows per CTA
    kA_zis<<<gA, 512, SMEM_KA>>>(x, Wis, bis);

    kP_rows<<<NCTA, 512, SMEM_P>>>(Wss, bss, out);
}

// round 16
// speedup vs baseline: 2.2640x; 1.0577x over previous
#include <cuda_runtime.h>
#include <cuda_bf16.h>
#include <cuda_fp16.h>
#include <stdint.h>
#include <math.h>

#define Bb   16
#define Cc   128
#define Hh   64
#define Ww   64
#define HID  128
#define OC   512
#define NCTA 128   // 16 b x 8 hid-blocks

typedef unsigned long long u64;

// Scratch (device globals). Transposed layouts (private to this kernel):
//   g_zis : [b][h][w][o]   (o contiguous, 512)
//   g_hbuf: [buf][b][w][c] (c contiguous, 128)
__device__ float    g_zis[(size_t)Bb*Hh*Ww*OC];
__device__ float    g_hbuf[2][Bb*Ww*HID];
__device__ unsigned g_cnt[32*32];
// per ob (4 x 128 o): 4 weight files (t0hi,t1hi,t0lo,t1lo), each [128][128] fp16 sw256
__device__ __half   g_wA[4][65536];

__device__ __forceinline__ unsigned ld_acq_gpu(const unsigned* p) {
    unsigned v;
    asm volatile("ld.global.acquire.gpu.u32 %0, [%1];" : "=r"(v) : "l"(p) : "memory");
    return v;
}
__device__ __forceinline__ void red_rel_gpu(unsigned* p, unsigned v) {
    asm volatile("red.release.gpu.global.add.u32 [%0], %1;" :: "l"(p), "r"(v) : "memory");
}
__device__ __forceinline__ void st_rel_gpu(unsigned* p, unsigned v) {
    asm volatile("st.global.release.gpu.u32 [%0], %1;" :: "l"(p), "r"(v) : "memory");
}
__device__ __forceinline__ uint32_t smem_u32(const void* p) {
    uint32_t a;
    asm("{ .reg .u64 t; cvta.to.shared.u64 t, %1; cvt.u32.u64 %0, t; }" : "=r"(a) : "l"(p));
    return a;
}

// ---- legacy tensor-core helpers (sm_80+ PTX) -------------------------------
__device__ __forceinline__ void ldsm_x4(uint32_t* r, uint32_t addr) {
    asm volatile("ldmatrix.sync.aligned.m8n8.x4.shared.b16 {%0,%1,%2,%3}, [%4];"
                 : "=r"(r[0]), "=r"(r[1]), "=r"(r[2]), "=r"(r[3]) : "r"(addr));
}
__device__ __forceinline__ void mma_bf16(float* d, const uint32_t* a, const uint32_t* b) {
    asm volatile("mma.sync.aligned.m16n8k16.row.col.f32.bf16.bf16.f32 "
                 "{%0,%1,%2,%3}, {%4,%5,%6,%7}, {%8,%9}, {%0,%1,%2,%3};"
                 : "+f"(d[0]), "+f"(d[1]), "+f"(d[2]), "+f"(d[3])
                 : "r"(a[0]), "r"(a[1]), "r"(a[2]), "r"(a[3]), "r"(b[0]), "r"(b[1]));
}
__device__ __forceinline__ void mma_fp16(float* d, const uint32_t* a, const uint32_t* b) {
    asm volatile("mma.sync.aligned.m16n8k16.row.col.f32.f16.f16.f32 "
                 "{%0,%1,%2,%3}, {%4,%5,%6,%7}, {%8,%9}, {%0,%1,%2,%3};"
                 : "+f"(d[0]), "+f"(d[1]), "+f"(d[2]), "+f"(d[3])
                 : "r"(a[0]), "r"(a[1]), "r"(a[2]), "r"(a[3]), "r"(b[0]), "r"(b[1]));
}

// swizzle: 16B chunks XOR'ed by (row & 7); row stride 256 bytes (K=128 fp16/bf16)
__device__ __forceinline__ uint32_t sw256(int row, int k) {
    return (uint32_t)(row*256 + ((((k >> 3) ^ (row & 7)) << 4) | ((k & 7) << 1)));
}

// ---------------------------------------------------------------------------
// kW_prep: W_is -> 4 preswizzled fp16 files per ob: f = t + 2*(lo?)
__global__ void kW_prep(const float* __restrict__ Wis) {
    int id = blockIdx.x * 256 + threadIdx.x;
    for (int it = 0; it < 16; ++it) {
        int idx = id + it*8192;               // 0 .. 131071
        int blk = idx >> 15;                  // ob 0..3
        int r   = idx & 32767;
        int ol  = r >> 8;                     // 0..127
        int k   = r & 255;
        int c = k >> 1, t = k & 1;
        float v = Wis[(size_t)(blk*128 + ol)*384 + c*3 + t];
        __half vh = __float2half_rn(v);
        __half vl = __float2half_rn(v - __half2float(vh));
        uint32_t off = sw256(ol, c) >> 1;
        g_wA[blk][t*16384 + off]           = vh;   // files 0,1 = t0hi, t1hi
        g_wA[blk][(2 + t)*16384 + off]     = vl;   // files 2,3 = t0lo, t1lo
    }
}

// ---------------------------------------------------------------------------
// Phase 1: masked input-to-state conv, Toeplitz-factored, 4 h-rows per CTA.
// P_t = W_t (128 o x 128 c) x X^T (64 w x 128 c); z[w][o] = P_1[w] + P_0[w-1].
#define KA_W_OFF  0          // 4 files x [128][256B]             131072
#define KA_XH_OFF 131072     // Xhi [64][256B]                     16384
#define KA_XL_OFF 147456     // Xlo                                16384
#define KA_ZB_OFF 163840     // union{ xs [128][64] f32 ; zbt0/zbt1 [64][132] f32 }
#define SMEM_KA   231424

__global__ void __launch_bounds__(512, 1)
kA_zis(const float* __restrict__ x,
       const float* __restrict__ Wis,
       const float* __restrict__ bis) {
    extern __shared__ char smc[];
    float* xs   = reinterpret_cast<float*>(smc + KA_ZB_OFF);   // [128][64]
    float* zbt0 = reinterpret_cast<float*>(smc + KA_ZB_OFF);   // [64][132]
    float* zbt1 = zbt0 + 8448;                                 // [64][132]
    uint32_t sb = smem_u32(smc);

    int b  = blockIdx.x >> 4;
    int hq = blockIdx.x & 15;
    int ob = blockIdx.y;
    int tid = threadIdx.x, wid = tid >> 5, lane = tid & 31;

    // stage preswizzled weight files once (float4 copy, L2-resident)
    {
        const float4* src = reinterpret_cast<const float4*>(g_wA[ob]);
        float4* dst = reinterpret_cast<float4*>(smc + KA_W_OFF);
#pragma unroll
        for (int it = 0; it < 16; ++it)
            dst[tid + it*512] = __ldg(&src[tid + it*512]);
    }

    // z-write mapping + bias preload
    int zw = tid >> 3, zq = tid & 7;
    float bv[16];
#pragma unroll
    for (int j = 0; j < 16; ++j) bv[j] = bis[ob*128 + zq*16 + j];

    // MMA mapping (identical lane math to kP; row stride 256B, 8 kt)
    int mt = wid & 7, nh = wid >> 3;
    int m0 = mt*16, n0 = nh*32;
    int sw8 = lane & 7;
    int csa = lane >> 4;
    int bm  = lane >> 3, csb = bm & 1;
    int rbo = (bm >> 1)*8 + (lane & 7);
    uint32_t aT0h = sb + KA_W_OFF + 0*32768 + (uint32_t)(m0 + (lane & 15))*256;
    uint32_t aT1h = sb + KA_W_OFF + 1*32768 + (uint32_t)(m0 + (lane & 15))*256;
    uint32_t aT0l = sb + KA_W_OFF + 2*32768 + (uint32_t)(m0 + (lane & 15))*256;
    uint32_t aT1l = sb + KA_W_OFF + 3*32768 + (uint32_t)(m0 + (lane & 15))*256;
    uint32_t b_r0 = (uint32_t)(n0 + rbo)*256;
    uint32_t b_r1 = (uint32_t)(n0 + 16 + rbo)*256;
    int er = lane >> 2, ec = (lane & 3)*2;

    for (int rr = 0; rr < 4; ++rr) {
        int h = hq*4 + rr;
        if (rr > 0) __syncthreads();       // zbt reads done before xs overwrite

        for (int idx = tid; idx < 8192; idx += 512)
            xs[idx] = x[(((size_t)b*Cc + (idx >> 6))*Hh + h)*Ww + (idx & 63)];
        __syncthreads();

        // build X^T hi/lo: B[w][c] = x[c][w], split fp16
        {
            int bw = tid & 63, seg = tid >> 6;
#pragma unroll 4
            for (int i = 0; i < 8; ++i) {
                int c = seg*16 + 2*i;
                float v0 = xs[c*64 + bw];
                float v1 = xs[(c+1)*64 + bw];
                __half h0 = __float2half_rn(v0), h1 = __float2half_rn(v1);
                __half l0 = __float2half_rn(v0 - __half2float(h0));
                __half l1 = __float2half_rn(v1 - __half2float(h1));
                uint32_t phi = (uint32_t)__half_as_ushort(h0) | ((uint32_t)__half_as_ushort(h1) << 16);
                uint32_t plo = (uint32_t)__half_as_ushort(l0) | ((uint32_t)__half_as_ushort(l1) << 16);
                uint32_t off = sw256(bw, c);
                *reinterpret_cast<uint32_t*>(smc + KA_XH_OFF + off) = phi;
                *reinterpret_cast<uint32_t*>(smc + KA_XL_OFF + off) = plo;
            }
        }
        __syncthreads();

        // factored GEMM: P_t accumulators, shared X fragments
        float acc[2][4][4];
#pragma unroll
        for (int t = 0; t < 2; ++t)
#pragma unroll
            for (int nt = 0; nt < 4; ++nt)
#pragma unroll
                for (int i = 0; i < 4; ++i) acc[t][nt][i] = 0.f;

#pragma unroll 2
        for (int kt = 0; kt < 8; ++kt) {
            uint32_t ca = (uint32_t)(((2*kt + csa) ^ sw8) << 4);
            uint32_t cb = (uint32_t)(((2*kt + csb) ^ sw8) << 4);
            uint32_t a0h[4], a1h[4], a0l[4], a1l[4], bh0[4], bh1[4], bl0[4], bl1[4];
            ldsm_x4(a0h, aT0h + ca);
            ldsm_x4(a1h, aT1h + ca);
            ldsm_x4(a0l, aT0l + ca);
            ldsm_x4(a1l, aT1l + ca);
            ldsm_x4(bh0, sb + KA_XH_OFF + b_r0 + cb);
            ldsm_x4(bh1, sb + KA_XH_OFF + b_r1 + cb);
            ldsm_x4(bl0, sb + KA_XL_OFF + b_r0 + cb);
            ldsm_x4(bl1, sb + KA_XL_OFF + b_r1 + cb);
            // tap 0: Whi*Xhi + Whi*Xlo + Wlo*Xhi
            mma_fp16(acc[0][0], a0h, bh0); mma_fp16(acc[0][1], a0h, bh0+2);
            mma_fp16(acc[0][2], a0h, bh1); mma_fp16(acc[0][3], a0h, bh1+2);
            mma_fp16(acc[0][0], a0h, bl0); mma_fp16(acc[0][1], a0h, bl0+2);
            mma_fp16(acc[0][2], a0h, bl1); mma_fp16(acc[0][3], a0h, bl1+2);
            mma_fp16(acc[0][0], a0l, bh0); mma_fp16(acc[0][1], a0l, bh0+2);
            mma_fp16(acc[0][2], a0l, bh1); mma_fp16(acc[0][3], a0l, bh1+2);
            // tap 1
            mma_fp16(acc[1][0], a1h, bh0); mma_fp16(acc[1][1], a1h, bh0+2);
            mma_fp16(acc[1][2], a1h, bh1); mma_fp16(acc[1][3], a1h, bh1+2);
            mma_fp16(acc[1][0], a1h, bl0); mma_fp16(acc[1][1], a1h, bl0+2);
            mma_fp16(acc[1][2], a1h, bl1); mma_fp16(acc[1][3], a1h, bl1+2);
            mma_fp16(acc[1][0], a1l, bh0); mma_fp16(acc[1][1], a1l, bh0+2);
            mma_fp16(acc[1][2], a1l, bh1); mma_fp16(acc[1][3], a1l, bh1+2);
        }
        __syncthreads();   // xs reads (B-build) done before zbt overwrite

        // epilogue: store TRANSPOSED zbt_t[w][o] (stride 132)
#pragma unroll
        for (int nt = 0; nt < 4; ++nt) {
            int col = n0 + nt*8 + ec;
            zbt0[col*132 + m0 + er]           = acc[0][nt][0];
            zbt0[(col + 1)*132 + m0 + er]     = acc[0][nt][1];
            zbt0[col*132 + m0 + er + 8]       = acc[0][nt][2];
            zbt0[(col + 1)*132 + m0 + er + 8] = acc[0][nt][3];
            zbt1[col*132 + m0 + er]           = acc[1][nt][0];
            zbt1[(col + 1)*132 + m0 + er]     = acc[1][nt][1];
            zbt1[col*132 + m0 + er + 8]       = acc[1][nt][2];
            zbt1[(col + 1)*132 + m0 + er + 8] = acc[1][nt][3];
        }
        __syncthreads();

        // write z_is[b][h][w][o] = P1[w] + P0[w-1] + bias (coalesced)
        {
            float* dst = &g_zis[(((size_t)b*Hh + h)*Ww + zw)*OC + ob*128 + zq*16];
#pragma unroll
            for (int j = 0; j < 16; j += 4) {
                float4 v = *reinterpret_cast<const float4*>(&zbt1[zw*132 + zq*16 + j]);
                if (zw > 0) {
                    float4 p = *reinterpret_cast<const float4*>(&zbt0[(zw-1)*132 + zq*16 + j]);
                    v.x += p.x; v.y += p.y; v.z += p.z; v.w += p.w;
                }
                v.x += bv[j]; v.y += bv[j+1]; v.z += bv[j+2]; v.w += bv[j+3];
                *reinterpret_cast<float4*>(dst + j) = v;
            }
        }
    }
}

// ---------------------------------------------------------------------------
// Phase 2: persistent recurrence, Toeplitz-factored tensor GEMM (R15, unchanged).
#define BH_OFF2 98304        // A_k at k*32768 (3 x [128][256B])
#define BL_OFF2 114688
#define ZS_OFF2 131072       // zsum 3 x [64][66] f32
#define SMEM_P  181760

__global__ void __launch_bounds__(512, 1)
kP_rows(const float* __restrict__ Wss,
        const float* __restrict__ bss,
        float* __restrict__ out) {
    extern __shared__ char smc[];
    float* zsum = reinterpret_cast<float*>(smc + ZS_OFF2);   // 3 x [64][66]
    uint32_t smem_base = smem_u32(smc);

    int b   = blockIdx.x >> 3;
    int hb  = blockIdx.x & 7;
    int tid = threadIdx.x;
    int wid = tid >> 5;
    int lane = tid & 31;
    unsigned* cnt  = &g_cnt[b*32];
    unsigned* cnt2 = &g_cnt[(16 + b)*32];

    // Build A_k files once: row 2ol = Whi, row 2ol+1 = Wlo, col = c
    for (int idx = tid; idx < 64*384; idx += 512) {
        int ol  = idx / 384;
        int rem = idx - ol*384;
        int o   = (ol >> 4)*128 + hb*16 + (ol & 15);
        float v = Wss[(size_t)o*384 + rem];
        int c = rem / 3, kk = rem - c*3;
        __nv_bfloat16 vh = __float2bfloat16_rn(v);
        __nv_bfloat16 vl = __float2bfloat16_rn(v - __bfloat162float(vh));
        char* base = smc + kk*32768;
        *reinterpret_cast<__nv_bfloat16*>(base + sw256(2*ol,     c)) = vh;
        *reinterpret_cast<__nv_bfloat16*>(base + sw256(2*ol + 1, c)) = vl;
    }

    // MMA warp mapping
    int mt = wid & 7, nh = wid >> 3;
    int m0 = mt*16, n0 = nh*32;
    int sw   = lane & 7;
    int csa  = lane >> 4;
    int bm   = lane >> 3;
    int csb  = bm & 1;
    int rbo  = (bm >> 1)*8 + (lane & 7);
    uint32_t aK0 = smem_base + 0*32768 + (uint32_t)(m0 + (lane & 15))*256;
    uint32_t aK1 = smem_base + 1*32768 + (uint32_t)(m0 + (lane & 15))*256;
    uint32_t aK2 = smem_base + 2*32768 + (uint32_t)(m0 + (lane & 15))*256;
    uint32_t brow0 = (uint32_t)(n0 + rbo)*256;
    uint32_t brow1 = (uint32_t)(n0 + 16 + rbo)*256;

    // gate-phase mapping: thread = (w = tid>>3, q = tid&7) -> channels 2q, 2q+1
    int gw = tid >> 3;
    int gq = tid & 7;
    int ch0 = hb*16 + 2*gq;
    float sbv[4][2];
#pragma unroll
    for (int g = 0; g < 4; ++g) {
        sbv[g][0] = bss[g*128 + ch0];
        sbv[g][1] = bss[g*128 + ch0 + 1];
    }
    float cst[2] = {0.f, 0.f};

    // epilogue mapping
    int er = lane >> 2, ec = (lane & 3)*2;
    int olA = mt*8 + (er >> 1);
    bool estore = ((lane & 4) == 0);

    __syncthreads();

    for (int r = 0; r < Hh; ++r) {
        // prefetch z_is[b][r][w][o] (coalesced)
        float2 zv[4];
        {
            const float* zrow = &g_zis[(((size_t)b*Hh + r)*Ww + gw)*OC];
#pragma unroll
            for (int g = 0; g < 4; ++g)
                zv[g] = *reinterpret_cast<const float2*>(&zrow[g*128 + ch0]);
        }

        if (r > 0) {
            if (tid == 0) {
                unsigned target = 8u * (unsigned)r;
                while (ld_acq_gpu(cnt) < target) __nanosleep(32);
            }
            __syncthreads();

            // B-build straight from g_hbuf[b][w][c] (coalesced float4 reads)
            {
                const float4* hsrc = reinterpret_cast<const float4*>(
                    g_hbuf[(r-1) & 1] + (size_t)b*Ww*HID);
#pragma unroll
                for (int it = 0; it < 4; ++it) {
                    int j = tid + it*512;
                    int w = j >> 5, c4 = j & 31;
                    float4 v = __ldcg(&hsrc[j]);
                    int c = c4*4;
                    __nv_bfloat16 h0 = __float2bfloat16_rn(v.x);
                    __nv_bfloat16 h1 = __float2bfloat16_rn(v.y);
                    __nv_bfloat16 h2 = __float2bfloat16_rn(v.z);
                    __nv_bfloat16 h3 = __float2bfloat16_rn(v.w);
                    __nv_bfloat16 l0 = __float2bfloat16_rn(v.x - __bfloat162float(h0));
                    __nv_bfloat16 l1 = __float2bfloat16_rn(v.y - __bfloat162float(h1));
                    __nv_bfloat16 l2 = __float2bfloat16_rn(v.z - __bfloat162float(h2));
                    __nv_bfloat16 l3 = __float2bfloat16_rn(v.w - __bfloat162float(h3));
                    uint32_t hiA = (uint32_t)__bfloat16_as_ushort(h0) |
                                   ((uint32_t)__bfloat16_as_ushort(h1) << 16);
                    uint32_t hiB = (uint32_t)__bfloat16_as_ushort(h2) |
                                   ((uint32_t)__bfloat16_as_ushort(h3) << 16);
                    uint32_t loA = (uint32_t)__bfloat16_as_ushort(l0) |
                                   ((uint32_t)__bfloat16_as_ushort(l1) << 16);
                    uint32_t loB = (uint32_t)__bfloat16_as_ushort(l2) |
                                   ((uint32_t)__bfloat16_as_ushort(l3) << 16);
                    uint32_t offA = sw256(w, c);
                    uint32_t offB = sw256(w, c + 2);
                    *reinterpret_cast<uint32_t*>(smc + BH_OFF2 + offA) = hiA;
                    *reinterpret_cast<uint32_t*>(smc + BH_OFF2 + offB) = hiB;
                    *reinterpret_cast<uint32_t*>(smc + BL_OFF2 + offA) = loA;
                    *reinterpret_cast<uint32_t*>(smc + BL_OFF2 + offB) = loB;
                }
            }
            __syncthreads();

            // 3-tap factored GEMM
            float acc[3][4][4];
#pragma unroll
            for (int k = 0; k < 3; ++k)
#pragma unroll
                for (int nt = 0; nt < 4; ++nt)
#pragma unroll
                    for (int i = 0; i < 4; ++i) acc[k][nt][i] = 0.f;

#pragma unroll 2
            for (int kt = 0; kt < 8; ++kt) {
                uint32_t ca = (uint32_t)(((2*kt + csa) ^ sw) << 4);
                uint32_t cb = (uint32_t)(((2*kt + csb) ^ sw) << 4);
                uint32_t a0[4], a1[4], a2[4], b0[4], b1[4];
                ldsm_x4(a0, aK0 + ca);
                ldsm_x4(a1, aK1 + ca);
                ldsm_x4(a2, aK2 + ca);
                ldsm_x4(b0, smem_base + BH_OFF2 + brow0 + cb);
                ldsm_x4(b1, smem_base + BH_OFF2 + brow1 + cb);
                mma_bf16(acc[0][0], a0, b0); mma_bf16(acc[0][1], a0, b0+2);
                mma_bf16(acc[0][2], a0, b1); mma_bf16(acc[0][3], a0, b1+2);
                mma_bf16(acc[1][0], a1, b0); mma_bf16(acc[1][1], a1, b0+2);
                mma_bf16(acc[1][2], a1, b1); mma_bf16(acc[1][3], a1, b1+2);
                mma_bf16(acc[2][0], a2, b0); mma_bf16(acc[2][1], a2, b0+2);
                mma_bf16(acc[2][2], a2, b1); mma_bf16(acc[2][3], a2, b1+2);
                ldsm_x4(b0, smem_base + BL_OFF2 + brow0 + cb);
                ldsm_x4(b1, smem_base + BL_OFF2 + brow1 + cb);
                mma_bf16(acc[0][0], a0, b0); mma_bf16(acc[0][1], a0, b0+2);
                mma_bf16(acc[0][2], a0, b1); mma_bf16(acc[0][3], a0, b1+2);
                mma_bf16(acc[1][0], a1, b0); mma_bf16(acc[1][1], a1, b0+2);
                mma_bf16(acc[1][2], a1, b1); mma_bf16(acc[1][3], a1, b1+2);
                mma_bf16(acc[2][0], a2, b0); mma_bf16(acc[2][1], a2, b0+2);
                mma_bf16(acc[2][2], a2, b1); mma_bf16(acc[2][3], a2, b1+2);
            }

            // epilogue: combine hi/lo row pairs (shfl.bfly 4), store zsum[k]
#pragma unroll
            for (int k = 0; k < 3; ++k) {
#pragma unroll
                for (int nt = 0; nt < 4; ++nt) {
                    int col = n0 + nt*8 + ec;
                    float s0 = acc[k][nt][0] + __shfl_xor_sync(0xffffffffu, acc[k][nt][0], 4);
                    float s1 = acc[k][nt][1] + __shfl_xor_sync(0xffffffffu, acc[k][nt][1], 4);
                    float s2 = acc[k][nt][2] + __shfl_xor_sync(0xffffffffu, acc[k][nt][2], 4);
                    float s3 = acc[k][nt][3] + __shfl_xor_sync(0xffffffffu, acc[k][nt][3], 4);
                    if (estore) {
                        *reinterpret_cast<float2*>(&zsum[k*4224 + olA*66 + col]) =
                            make_float2(s0, s1);
                        *reinterpret_cast<float2*>(&zsum[k*4224 + (olA + 4)*66 + col]) =
                            make_float2(s2, s3);
                    }
                }
            }
        }
        __syncthreads();

        // gates at (w = gw, channels ch0, ch0+1)
        float hres[2];
#pragma unroll
        for (int j = 0; j < 2; ++j) {
            int cl = 2*gq + j;
            float zs[4];
#pragma unroll
            for (int g = 0; g < 4; ++g) {
                float s = 0.f;
                if (r > 0) {
                    int olg = g*16 + cl;
                    if (gw >= 1)  s += zsum[0*4224 + olg*66 + (gw - 1)];
                    s += zsum[1*4224 + olg*66 + gw];
                    if (gw <= 62) s += zsum[2*4224 + olg*66 + (gw + 1)];
                }
                zs[g] = s;
            }
            float zi = zs[0] + sbv[0][j] + (j ? zv[0].y : zv[0].x);
            float zf = zs[1] + sbv[1][j] + (j ? zv[1].y : zv[1].x);
            float zo = zs[2] + sbv[2][j] + (j ? zv[2].y : zv[2].x);
            float zg = zs[3] + sbv[3][j] + (j ? zv[3].y : zv[3].x);
            float ig = 1.f / (1.f + __expf(-zi));
            float fg = 1.f / (1.f + __expf(-zf));
            float og = 1.f / (1.f + __expf(-zo));
            float gg = tanhf(zg);
            float cn = fg*cst[j] + ig*gg;
            cst[j] = cn;
            hres[j] = og * tanhf(cn);
        }
        out[(((size_t)b*HID + ch0)*Hh + r)*Ww + gw]     = hres[0];
        out[(((size_t)b*HID + ch0 + 1)*Hh + r)*Ww + gw] = hres[1];

        if (r < Hh - 1) {
            __stcg(reinterpret_cast<float2*>(
                &g_hbuf[r & 1][((size_t)b*Ww + gw)*HID + ch0]),
                make_float2(hres[0], hres[1]));
            __syncthreads();
            if (tid == 0) red_rel_gpu(cnt, 1u);
        }
    }

    // self-reset counters for graph replays
    __syncthreads();
    if (tid == 0) {
        red_rel_gpu(cnt2, 1u);
        if (hb == 0) {
            while (ld_acq_gpu(cnt2) < 8u) __nanosleep(32);
            st_rel_gpu(cnt,  0u);
            st_rel_gpu(cnt2, 0u);
        }
    }
}

// ---------------------------------------------------------------------------
extern "C" void kernel_launch(void* const* d_in, const int* in_sizes, int n_in,
                              void* d_out, int out_size) {
    const float* x   = (const float*)d_in[0];
    const float* Wis = (const float*)d_in[1];
    const float* bis = (const float*)d_in[2];
    const float* Wss = (const float*)d_in[3];
    const float* bss = (const float*)d_in[4];
    float* out = (float*)d_out;

    cudaFuncSetAttribute(kA_zis,  cudaFuncAttributeMaxDynamicSharedMemorySize, SMEM_KA);
    cudaFuncSetAttribute(kP_rows, cudaFuncAttributeMaxDynamicSharedMemorySize, SMEM_P);

    kW_prep<<<32, 256>>>(Wis);

    dim3 gA(Bb*16, OC/128);   // 4 h-rows per CTA
    kA_zis<<<gA, 512, SMEM_KA>>>(x, Wis, bis);

    kP_rows<<<NCTA, 512, SMEM_P>>>(Wss, bss, out);
}

// round 17
// speedup vs baseline: 2.2848x; 1.0092x over previous
#include <cuda_runtime.h>
#include <cuda_bf16.h>
#include <cuda_fp16.h>
#include <stdint.h>
#include <math.h>

#define Bb   16
#define Cc   128
#define Hh   64
#define Ww   64
#define HID  128
#define OC   512
#define NCTA 128   // 16 b x 8 hid-blocks

typedef unsigned long long u64;

// Scratch (device globals). Transposed layouts (private to this kernel):
//   g_zis : [b][h][w][o]   (o contiguous, 512)
//   g_hpH/g_hpL: [buf][b][w][64 c-pairs] packed bf16x2 hi/lo of h
__device__ float    g_zis[(size_t)Bb*Hh*Ww*OC];
__device__ uint32_t g_hpH[2][Bb*Ww*64];
__device__ uint32_t g_hpL[2][Bb*Ww*64];
__device__ unsigned g_cnt[32*32];
// per ob (4 x 128 o): 4 weight files (t0hi,t1hi,t0lo,t1lo), each [128][128] fp16 sw256
__device__ __half   g_wA[4][65536];

__device__ __forceinline__ unsigned ld_acq_gpu(const unsigned* p) {
    unsigned v;
    asm volatile("ld.global.acquire.gpu.u32 %0, [%1];" : "=r"(v) : "l"(p) : "memory");
    return v;
}
__device__ __forceinline__ void red_rel_gpu(unsigned* p, unsigned v) {
    asm volatile("red.release.gpu.global.add.u32 [%0], %1;" :: "l"(p), "r"(v) : "memory");
}
__device__ __forceinline__ void st_rel_gpu(unsigned* p, unsigned v) {
    asm volatile("st.global.release.gpu.u32 [%0], %1;" :: "l"(p), "r"(v) : "memory");
}
__device__ __forceinline__ uint32_t smem_u32(const void* p) {
    uint32_t a;
    asm("{ .reg .u64 t; cvta.to.shared.u64 t, %1; cvt.u32.u64 %0, t; }" : "=r"(a) : "l"(p));
    return a;
}

// ---- legacy tensor-core helpers (sm_80+ PTX) -------------------------------
__device__ __forceinline__ void ldsm_x4(uint32_t* r, uint32_t addr) {
    asm volatile("ldmatrix.sync.aligned.m8n8.x4.shared.b16 {%0,%1,%2,%3}, [%4];"
                 : "=r"(r[0]), "=r"(r[1]), "=r"(r[2]), "=r"(r[3]) : "r"(addr));
}
__device__ __forceinline__ void mma_bf16(float* d, const uint32_t* a, const uint32_t* b) {
    asm volatile("mma.sync.aligned.m16n8k16.row.col.f32.bf16.bf16.f32 "
                 "{%0,%1,%2,%3}, {%4,%5,%6,%7}, {%8,%9}, {%0,%1,%2,%3};"
                 : "+f"(d[0]), "+f"(d[1]), "+f"(d[2]), "+f"(d[3])
                 : "r"(a[0]), "r"(a[1]), "r"(a[2]), "r"(a[3]), "r"(b[0]), "r"(b[1]));
}
__device__ __forceinline__ void mma_fp16(float* d, const uint32_t* a, const uint32_t* b) {
    asm volatile("mma.sync.aligned.m16n8k16.row.col.f32.f16.f16.f32 "
                 "{%0,%1,%2,%3}, {%4,%5,%6,%7}, {%8,%9}, {%0,%1,%2,%3};"
                 : "+f"(d[0]), "+f"(d[1]), "+f"(d[2]), "+f"(d[3])
                 : "r"(a[0]), "r"(a[1]), "r"(a[2]), "r"(a[3]), "r"(b[0]), "r"(b[1]));
}

// swizzle: 16B chunks XOR'ed by (row & 7); row stride 256 bytes (K=128 fp16/bf16)
__device__ __forceinline__ uint32_t sw256(int row, int k) {
    return (uint32_t)(row*256 + ((((k >> 3) ^ (row & 7)) << 4) | ((k & 7) << 1)));
}

// ---------------------------------------------------------------------------
// kW_prep: W_is -> 4 preswizzled fp16 files per ob: f = t + 2*(lo?)
__global__ void kW_prep(const float* __restrict__ Wis) {
    int id = blockIdx.x * 256 + threadIdx.x;
    for (int it = 0; it < 16; ++it) {
        int idx = id + it*8192;               // 0 .. 131071
        int blk = idx >> 15;                  // ob 0..3
        int r   = idx & 32767;
        int ol  = r >> 8;                     // 0..127
        int k   = r & 255;
        int c = k >> 1, t = k & 1;
        float v = Wis[(size_t)(blk*128 + ol)*384 + c*3 + t];
        __half vh = __float2half_rn(v);
        __half vl = __float2half_rn(v - __half2float(vh));
        uint32_t off = sw256(ol, c) >> 1;
        g_wA[blk][t*16384 + off]           = vh;
        g_wA[blk][(2 + t)*16384 + off]     = vl;
    }
}

// ---------------------------------------------------------------------------
// Phase 1: masked input-to-state conv, Toeplitz-factored, 8 h-rows per CTA.
// P_t = W_t (128 o x 128 c) x X^T (64 w x 128 c); z[w][o] = P_1[w] + P_0[w-1].
#define KA_W_OFF  0          // 4 files x [128][256B]             131072
#define KA_XH_OFF 131072     // Xhi [64][256B]                     16384
#define KA_XL_OFF 147456     // Xlo                                16384
#define KA_ZB_OFF 163840     // union{ xs [128][64] f32 ; zbt0/zbt1 [64][132] f32 }
#define SMEM_KA   231424

__global__ void __launch_bounds__(512, 1)
kA_zis(const float* __restrict__ x,
       const float* __restrict__ Wis,
       const float* __restrict__ bis) {
    extern __shared__ char smc[];
    float* xs   = reinterpret_cast<float*>(smc + KA_ZB_OFF);   // [128][64]
    float* zbt0 = reinterpret_cast<float*>(smc + KA_ZB_OFF);   // [64][132]
    float* zbt1 = zbt0 + 8448;                                 // [64][132]
    uint32_t sb = smem_u32(smc);

    int b  = blockIdx.x >> 3;
    int hq = blockIdx.x & 7;
    int ob = blockIdx.y;
    int tid = threadIdx.x, wid = tid >> 5, lane = tid & 31;

    // stage preswizzled weight files once (float4 copy, L2-resident)
    {
        const float4* src = reinterpret_cast<const float4*>(g_wA[ob]);
        float4* dst = reinterpret_cast<float4*>(smc + KA_W_OFF);
#pragma unroll
        for (int it = 0; it < 16; ++it)
            dst[tid + it*512] = __ldg(&src[tid + it*512]);
    }

    // z-write mapping + bias preload
    int zw = tid >> 3, zq = tid & 7;
    float bv[16];
#pragma unroll
    for (int j = 0; j < 16; ++j) bv[j] = bis[ob*128 + zq*16 + j];

    // MMA mapping
    int mt = wid & 7, nh = wid >> 3;
    int m0 = mt*16, n0 = nh*32;
    int sw8 = lane & 7;
    int csa = lane >> 4;
    int bm  = lane >> 3, csb = bm & 1;
    int rbo = (bm >> 1)*8 + (lane & 7);
    uint32_t aT0h = sb + KA_W_OFF + 0*32768 + (uint32_t)(m0 + (lane & 15))*256;
    uint32_t aT1h = sb + KA_W_OFF + 1*32768 + (uint32_t)(m0 + (lane & 15))*256;
    uint32_t aT0l = sb + KA_W_OFF + 2*32768 + (uint32_t)(m0 + (lane & 15))*256;
    uint32_t aT1l = sb + KA_W_OFF + 3*32768 + (uint32_t)(m0 + (lane & 15))*256;
    uint32_t b_r0 = (uint32_t)(n0 + rbo)*256;
    uint32_t b_r1 = (uint32_t)(n0 + 16 + rbo)*256;
    int er = lane >> 2, ec = (lane & 3)*2;

    for (int rr = 0; rr < 8; ++rr) {
        int h = hq*8 + rr;
        if (rr > 0) __syncthreads();       // zbt reads done before xs overwrite

        for (int idx = tid; idx < 8192; idx += 512)
            xs[idx] = x[(((size_t)b*Cc + (idx >> 6))*Hh + h)*Ww + (idx & 63)];
        __syncthreads();

        // build X^T hi/lo: B[w][c] = x[c][w], split fp16
        {
            int bw = tid & 63, seg = tid >> 6;
#pragma unroll 4
            for (int i = 0; i < 8; ++i) {
                int c = seg*16 + 2*i;
                float v0 = xs[c*64 + bw];
                float v1 = xs[(c+1)*64 + bw];
                __half h0 = __float2half_rn(v0), h1 = __float2half_rn(v1);
                __half l0 = __float2half_rn(v0 - __half2float(h0));
                __half l1 = __float2half_rn(v1 - __half2float(h1));
                uint32_t phi = (uint32_t)__half_as_ushort(h0) | ((uint32_t)__half_as_ushort(h1) << 16);
                uint32_t plo = (uint32_t)__half_as_ushort(l0) | ((uint32_t)__half_as_ushort(l1) << 16);
                uint32_t off = sw256(bw, c);
                *reinterpret_cast<uint32_t*>(smc + KA_XH_OFF + off) = phi;
                *reinterpret_cast<uint32_t*>(smc + KA_XL_OFF + off) = plo;
            }
        }
        __syncthreads();

        // factored GEMM: P_t accumulators, shared X fragments
        float acc[2][4][4];
#pragma unroll
        for (int t = 0; t < 2; ++t)
#pragma unroll
            for (int nt = 0; nt < 4; ++nt)
#pragma unroll
                for (int i = 0; i < 4; ++i) acc[t][nt][i] = 0.f;

#pragma unroll 2
        for (int kt = 0; kt < 8; ++kt) {
            uint32_t ca = (uint32_t)(((2*kt + csa) ^ sw8) << 4);
            uint32_t cb = (uint32_t)(((2*kt + csb) ^ sw8) << 4);
            uint32_t a0h[4], a1h[4], a0l[4], a1l[4], bh0[4], bh1[4], bl0[4], bl1[4];
            ldsm_x4(a0h, aT0h + ca);
            ldsm_x4(a1h, aT1h + ca);
            ldsm_x4(a0l, aT0l + ca);
            ldsm_x4(a1l, aT1l + ca);
            ldsm_x4(bh0, sb + KA_XH_OFF + b_r0 + cb);
            ldsm_x4(bh1, sb + KA_XH_OFF + b_r1 + cb);
            ldsm_x4(bl0, sb + KA_XL_OFF + b_r0 + cb);
            ldsm_x4(bl1, sb + KA_XL_OFF + b_r1 + cb);
            // tap 0: Whi*Xhi + Whi*Xlo + Wlo*Xhi
            mma_fp16(acc[0][0], a0h, bh0); mma_fp16(acc[0][1], a0h, bh0+2);
            mma_fp16(acc[0][2], a0h, bh1); mma_fp16(acc[0][3], a0h, bh1+2);
            mma_fp16(acc[0][0], a0h, bl0); mma_fp16(acc[0][1], a0h, bl0+2);
            mma_fp16(acc[0][2], a0h, bl1); mma_fp16(acc[0][3], a0h, bl1+2);
            mma_fp16(acc[0][0], a0l, bh0); mma_fp16(acc[0][1], a0l, bh0+2);
            mma_fp16(acc[0][2], a0l, bh1); mma_fp16(acc[0][3], a0l, bh1+2);
            // tap 1
            mma_fp16(acc[1][0], a1h, bh0); mma_fp16(acc[1][1], a1h, bh0+2);
            mma_fp16(acc[1][2], a1h, bh1); mma_fp16(acc[1][3], a1h, bh1+2);
            mma_fp16(acc[1][0], a1h, bl0); mma_fp16(acc[1][1], a1h, bl0+2);
            mma_fp16(acc[1][2], a1h, bl1); mma_fp16(acc[1][3], a1h, bl1+2);
            mma_fp16(acc[1][0], a1l, bh0); mma_fp16(acc[1][1], a1l, bh0+2);
            mma_fp16(acc[1][2], a1l, bh1); mma_fp16(acc[1][3], a1l, bh1+2);
        }
        __syncthreads();   // xs reads (B-build) done before zbt overwrite

        // epilogue: store TRANSPOSED zbt_t[w][o] (stride 132)
#pragma unroll
        for (int nt = 0; nt < 4; ++nt) {
            int col = n0 + nt*8 + ec;
            zbt0[col*132 + m0 + er]           = acc[0][nt][0];
            zbt0[(col + 1)*132 + m0 + er]     = acc[0][nt][1];
            zbt0[col*132 + m0 + er + 8]       = acc[0][nt][2];
            zbt0[(col + 1)*132 + m0 + er + 8] = acc[0][nt][3];
            zbt1[col*132 + m0 + er]           = acc[1][nt][0];
            zbt1[(col + 1)*132 + m0 + er]     = acc[1][nt][1];
            zbt1[col*132 + m0 + er + 8]       = acc[1][nt][2];
            zbt1[(col + 1)*132 + m0 + er + 8] = acc[1][nt][3];
        }
        __syncthreads();

        // write z_is[b][h][w][o] = P1[w] + P0[w-1] + bias (coalesced)
        {
            float* dst = &g_zis[(((size_t)b*Hh + h)*Ww + zw)*OC + ob*128 + zq*16];
#pragma unroll
            for (int j = 0; j < 16; j += 4) {
                float4 v = *reinterpret_cast<const float4*>(&zbt1[zw*132 + zq*16 + j]);
                if (zw > 0) {
                    float4 p = *reinterpret_cast<const float4*>(&zbt0[(zw-1)*132 + zq*16 + j]);
                    v.x += p.x; v.y += p.y; v.z += p.z; v.w += p.w;
                }
                v.x += bv[j]; v.y += bv[j+1]; v.z += bv[j+2]; v.w += bv[j+3];
                *reinterpret_cast<float4*>(dst + j) = v;
            }
        }
    }
}

// ---------------------------------------------------------------------------
// Phase 2: persistent recurrence, Toeplitz-factored tensor GEMM.
// h exchanged PRE-SPLIT (bf16 hi/lo packed pairs) -> B-build is a pure copy.
#define BH_OFF2 98304        // A_k at k*32768 (3 x [128][256B])
#define BL_OFF2 114688
#define ZS_OFF2 131072       // zsum 3 x [64][66] f32
#define SMEM_P  181760

__global__ void __launch_bounds__(512, 1)
kP_rows(const float* __restrict__ Wss,
        const float* __restrict__ bss,
        float* __restrict__ out) {
    extern __shared__ char smc[];
    float* zsum = reinterpret_cast<float*>(smc + ZS_OFF2);   // 3 x [64][66]
    uint32_t smem_base = smem_u32(smc);

    int b   = blockIdx.x >> 3;
    int hb  = blockIdx.x & 7;
    int tid = threadIdx.x;
    int wid = tid >> 5;
    int lane = tid & 31;
    unsigned* cnt  = &g_cnt[b*32];
    unsigned* cnt2 = &g_cnt[(16 + b)*32];

    // Build A_k files once: row 2ol = Whi, row 2ol+1 = Wlo, col = c
    for (int idx = tid; idx < 64*384; idx += 512) {
        int ol  = idx / 384;
        int rem = idx - ol*384;
        int o   = (ol >> 4)*128 + hb*16 + (ol & 15);
        float v = Wss[(size_t)o*384 + rem];
        int c = rem / 3, kk = rem - c*3;
        __nv_bfloat16 vh = __float2bfloat16_rn(v);
        __nv_bfloat16 vl = __float2bfloat16_rn(v - __bfloat162float(vh));
        char* base = smc + kk*32768;
        *reinterpret_cast<__nv_bfloat16*>(base + sw256(2*ol,     c)) = vh;
        *reinterpret_cast<__nv_bfloat16*>(base + sw256(2*ol + 1, c)) = vl;
    }

    // MMA warp mapping
    int mt = wid & 7, nh = wid >> 3;
    int m0 = mt*16, n0 = nh*32;
    int sw   = lane & 7;
    int csa  = lane >> 4;
    int bm   = lane >> 3;
    int csb  = bm & 1;
    int rbo  = (bm >> 1)*8 + (lane & 7);
    uint32_t aK0 = smem_base + 0*32768 + (uint32_t)(m0 + (lane & 15))*256;
    uint32_t aK1 = smem_base + 1*32768 + (uint32_t)(m0 + (lane & 15))*256;
    uint32_t aK2 = smem_base + 2*32768 + (uint32_t)(m0 + (lane & 15))*256;
    uint32_t brow0 = (uint32_t)(n0 + rbo)*256;
    uint32_t brow1 = (uint32_t)(n0 + 16 + rbo)*256;

    // gate-phase mapping: thread = (w = tid>>3, q = tid&7) -> channels 2q, 2q+1
    int gw = tid >> 3;
    int gq = tid & 7;
    int ch0 = hb*16 + 2*gq;
    float sbv[4][2];
#pragma unroll
    for (int g = 0; g < 4; ++g) {
        sbv[g][0] = bss[g*128 + ch0];
        sbv[g][1] = bss[g*128 + ch0 + 1];
    }
    float cst[2] = {0.f, 0.f};
    int hp_idx = hb*8 + gq;              // c-pair index this thread publishes

    // epilogue mapping
    int er = lane >> 2, ec = (lane & 3)*2;
    int olA = mt*8 + (er >> 1);
    bool estore = ((lane & 4) == 0);

    __syncthreads();

    for (int r = 0; r < Hh; ++r) {
        // prefetch z_is[b][r][w][o] (coalesced)
        float2 zv[4];
        {
            const float* zrow = &g_zis[(((size_t)b*Hh + r)*Ww + gw)*OC];
#pragma unroll
            for (int g = 0; g < 4; ++g)
                zv[g] = *reinterpret_cast<const float2*>(&zrow[g*128 + ch0]);
        }

        if (r > 0) {
            if (tid == 0) {
                unsigned target = 8u * (unsigned)r;
                while (ld_acq_gpu(cnt) < target) __nanosleep(32);
            }
            __syncthreads();

            // B-build: pure copy of pre-split packed h (uint4 = one 16B chunk)
            {
                const uint32_t* hH = g_hpH[(r-1) & 1] + (size_t)b*Ww*64;
                const uint32_t* hL = g_hpL[(r-1) & 1] + (size_t)b*Ww*64;
#pragma unroll
                for (int it = 0; it < 2; ++it) {
                    int idx = tid + it*512;          // 0..1023
                    int w = idx >> 4, q = idx & 15;  // chunk q covers c=8q..8q+7
                    uint32_t doff = (uint32_t)(w*256 + ((q ^ (w & 7)) << 4));
                    uint4 vh = __ldcg(reinterpret_cast<const uint4*>(hH + w*64 + q*4));
                    *reinterpret_cast<uint4*>(smc + BH_OFF2 + doff) = vh;
                    uint4 vl = __ldcg(reinterpret_cast<const uint4*>(hL + w*64 + q*4));
                    *reinterpret_cast<uint4*>(smc + BL_OFF2 + doff) = vl;
                }
            }
            __syncthreads();

            // 3-tap factored GEMM
            float acc[3][4][4];
#pragma unroll
            for (int k = 0; k < 3; ++k)
#pragma unroll
                for (int nt = 0; nt < 4; ++nt)
#pragma unroll
                    for (int i = 0; i < 4; ++i) acc[k][nt][i] = 0.f;

#pragma unroll 2
            for (int kt = 0; kt < 8; ++kt) {
                uint32_t ca = (uint32_t)(((2*kt + csa) ^ sw) << 4);
                uint32_t cb = (uint32_t)(((2*kt + csb) ^ sw) << 4);
                uint32_t a0[4], a1[4], a2[4], b0[4], b1[4];
                ldsm_x4(a0, aK0 + ca);
                ldsm_x4(a1, aK1 + ca);
                ldsm_x4(a2, aK2 + ca);
                ldsm_x4(b0, smem_base + BH_OFF2 + brow0 + cb);
                ldsm_x4(b1, smem_base + BH_OFF2 + brow1 + cb);
                mma_bf16(acc[0][0], a0, b0); mma_bf16(acc[0][1], a0, b0+2);
                mma_bf16(acc[0][2], a0, b1); mma_bf16(acc[0][3], a0, b1+2);
                mma_bf16(acc[1][0], a1, b0); mma_bf16(acc[1][1], a1, b0+2);
                mma_bf16(acc[1][2], a1, b1); mma_bf16(acc[1][3], a1, b1+2);
                mma_bf16(acc[2][0], a2, b0); mma_bf16(acc[2][1], a2, b0+2);
                mma_bf16(acc[2][2], a2, b1); mma_bf16(acc[2][3], a2, b1+2);
                ldsm_x4(b0, smem_base + BL_OFF2 + brow0 + cb);
                ldsm_x4(b1, smem_base + BL_OFF2 + brow1 + cb);
                mma_bf16(acc[0][0], a0, b0); mma_bf16(acc[0][1], a0, b0+2);
                mma_bf16(acc[0][2], a0, b1); mma_bf16(acc[0][3], a0, b1+2);
                mma_bf16(acc[1][0], a1, b0); mma_bf16(acc[1][1], a1, b0+2);
                mma_bf16(acc[1][2], a1, b1); mma_bf16(acc[1][3], a1, b1+2);
                mma_bf16(acc[2][0], a2, b0); mma_bf16(acc[2][1], a2, b0+2);
                mma_bf16(acc[2][2], a2, b1); mma_bf16(acc[2][3], a2, b1+2);
            }

            // epilogue: combine hi/lo row pairs (shfl.bfly 4), store zsum[k]
#pragma unroll
            for (int k = 0; k < 3; ++k) {
#pragma unroll
                for (int nt = 0; nt < 4; ++nt) {
                    int col = n0 + nt*8 + ec;
                    float s0 = acc[k][nt][0] + __shfl_xor_sync(0xffffffffu, acc[k][nt][0], 4);
                    float s1 = acc[k][nt][1] + __shfl_xor_sync(0xffffffffu, acc[k][nt][1], 4);
                    float s2 = acc[k][nt][2] + __shfl_xor_sync(0xffffffffu, acc[k][nt][2], 4);
                    float s3 = acc[k][nt][3] + __shfl_xor_sync(0xffffffffu, acc[k][nt][3], 4);
                    if (estore) {
                        *reinterpret_cast<float2*>(&zsum[k*4224 + olA*66 + col]) =
                            make_float2(s0, s1);
                        *reinterpret_cast<float2*>(&zsum[k*4224 + (olA + 4)*66 + col]) =
                            make_float2(s2, s3);
                    }
                }
            }
        }
        __syncthreads();

        // gates at (w = gw, channels ch0, ch0+1)
        float hres[2];
#pragma unroll
        for (int j = 0; j < 2; ++j) {
            int cl = 2*gq + j;
            float zs[4];
#pragma unroll
            for (int g = 0; g < 4; ++g) {
                float s = 0.f;
                if (r > 0) {
                    int olg = g*16 + cl;
                    if (gw >= 1)  s += zsum[0*4224 + olg*66 + (gw - 1)];
                    s += zsum[1*4224 + olg*66 + gw];
                    if (gw <= 62) s += zsum[2*4224 + olg*66 + (gw + 1)];
                }
                zs[g] = s;
            }
            float zi = zs[0] + sbv[0][j] + (j ? zv[0].y : zv[0].x);
            float zf = zs[1] + sbv[1][j] + (j ? zv[1].y : zv[1].x);
            float zo = zs[2] + sbv[2][j] + (j ? zv[2].y : zv[2].x);
            float zg = zs[3] + sbv[3][j] + (j ? zv[3].y : zv[3].x);
            float ig = 1.f / (1.f + __expf(-zi));
            float fg = 1.f / (1.f + __expf(-zf));
            float og = 1.f / (1.f + __expf(-zo));
            float gg = tanhf(zg);
            float cn = fg*cst[j] + ig*gg;
            cst[j] = cn;
            hres[j] = og * tanhf(cn);
        }
        out[(((size_t)b*HID + ch0)*Hh + r)*Ww + gw]     = hres[0];
        out[(((size_t)b*HID + ch0 + 1)*Hh + r)*Ww + gw] = hres[1];

        if (r < Hh - 1) {
            // publish PRE-SPLIT h: bf16 hi/lo packed pairs (identical split
            // to what the consumer used to compute — bit-identical math)
            __nv_bfloat16 h0 = __float2bfloat16_rn(hres[0]);
            __nv_bfloat16 h1 = __float2bfloat16_rn(hres[1]);
            __nv_bfloat16 l0 = __float2bfloat16_rn(hres[0] - __bfloat162float(h0));
            __nv_bfloat16 l1 = __float2bfloat16_rn(hres[1] - __bfloat162float(h1));
            uint32_t pH = (uint32_t)__bfloat16_as_ushort(h0) |
                          ((uint32_t)__bfloat16_as_ushort(h1) << 16);
            uint32_t pL = (uint32_t)__bfloat16_as_ushort(l0) |
                          ((uint32_t)__bfloat16_as_ushort(l1) << 16);
            size_t poff = ((size_t)b*Ww + gw)*64 + hp_idx;
            __stcg(&g_hpH[r & 1][poff], pH);
            __stcg(&g_hpL[r & 1][poff], pL);
            __syncthreads();
            if (tid == 0) red_rel_gpu(cnt, 1u);
        }
    }

    // self-reset counters for graph replays
    __syncthreads();
    if (tid == 0) {
        red_rel_gpu(cnt2, 1u);
        if (hb == 0) {
            while (ld_acq_gpu(cnt2) < 8u) __nanosleep(32);
            st_rel_gpu(cnt,  0u);
            st_rel_gpu(cnt2, 0u);
        }
    }
}

// ---------------------------------------------------------------------------
extern "C" void kernel_launch(void* const* d_in, const int* in_sizes, int n_in,
                              void* d_out, int out_size) {
    const float* x   = (const float*)d_in[0];
    const float* Wis = (const float*)d_in[1];
    const float* bis = (const float*)d_in[2];
    const float* Wss = (const float*)d_in[3];
    const float* bss = (const float*)d_in[4];
    float* out = (float*)d_out;

    cudaFuncSetAttribute(kA_zis,  cudaFuncAttributeMaxDynamicSharedMemorySize, SMEM_KA);
    cudaFuncSetAttribute(kP_rows, cudaFuncAttributeMaxDynamicSharedMemorySize, SMEM_P);

    kW_prep<<<32, 256>>>(Wis);

    dim3 gA(Bb*8, OC/128);   // 8 h-rows per CTA
    kA_zis<<<gA, 512, SMEM_KA>>>(x, Wis, bis);

    kP_rows<<<NCTA, 512, SMEM_P>>>(Wss, bss, out);
}